// round 1
// baseline (speedup 1.0000x reference)
#include <cuda_runtime.h>
#include <cstdint>

#define NN 50000
#define EE 800000
#define HD 256
#define DESW 768

// ---------------- scratch (device globals; no runtime alloc) ----------------
__device__ __align__(16) float g_xA[(size_t)NN * HD];        // 51.2 MB
__device__ __align__(16) float g_xB[(size_t)NN * HD];        // 51.2 MB
__device__ __align__(16) float g_h[(size_t)3 * NN * HD];     // 153.6 MB  [rel0 | rel1 | root]
__device__ __align__(16) float g_agg[(size_t)2 * NN * HD];   // 102.4 MB
__device__ __align__(16) float g_dinv[2 * NN];
__device__ __align__(16) int   g_cnt[2 * NN];

__device__ __forceinline__ float actf(float v, int act) {
    if (act == 1) return v > 0.f ? v : 0.01f * v;   // leaky relu
    if (act == 2) return v > 0.f ? v : 0.f;         // relu
    return v;
}

// ---------------- 64x64 tile fp32 GEMM core (BK=16, 256 threads) ------------
// C[m0..m0+63, 0..63] = act(A[m0.., :K] * B[:K, 0..63] + bias[0..63])
// A row-major lda, B row-major ldb, C row-major ldc. B/bias/C pre-offset to col tile.
__device__ __forceinline__ void gemm_tile(
    const float* __restrict__ A, int lda,
    const float* __restrict__ B, int ldb,
    const float* __restrict__ bias,
    float* __restrict__ C, int ldc,
    int M, int K, int m0, int act)
{
    __shared__ float As[16][64];   // [k][row]
    __shared__ float Bs[16][64];   // [k][col]
    const int t   = threadIdx.x;
    const int tx  = t & 15, ty = t >> 4;     // 16x16 thread grid, 4x4 micro-tile
    const int arow = t >> 2, akq = t & 3;    // A loader: 64 rows x 4 float4
    const int bkr  = t >> 4, bcq = t & 15;   // B loader: 16 rows x 16 float4

    float acc[4][4];
#pragma unroll
    for (int i = 0; i < 4; i++)
#pragma unroll
        for (int j = 0; j < 4; j++) acc[i][j] = 0.f;

    for (int k0 = 0; k0 < K; k0 += 16) {
        float4 av = make_float4(0.f, 0.f, 0.f, 0.f);
        int gr = m0 + arow;
        if (gr < M) av = *(const float4*)(A + (size_t)gr * lda + k0 + akq * 4);
        As[akq * 4 + 0][arow] = av.x;
        As[akq * 4 + 1][arow] = av.y;
        As[akq * 4 + 2][arow] = av.z;
        As[akq * 4 + 3][arow] = av.w;

        float4 bv = *(const float4*)(B + (size_t)(k0 + bkr) * ldb + bcq * 4);
        *(float4*)&Bs[bkr][bcq * 4] = bv;
        __syncthreads();

#pragma unroll
        for (int kk = 0; kk < 16; kk++) {
            float4 a = *(const float4*)&As[kk][ty * 4];
            float4 b = *(const float4*)&Bs[kk][tx * 4];
            acc[0][0] += a.x * b.x; acc[0][1] += a.x * b.y; acc[0][2] += a.x * b.z; acc[0][3] += a.x * b.w;
            acc[1][0] += a.y * b.x; acc[1][1] += a.y * b.y; acc[1][2] += a.y * b.z; acc[1][3] += a.y * b.w;
            acc[2][0] += a.z * b.x; acc[2][1] += a.z * b.y; acc[2][2] += a.z * b.z; acc[2][3] += a.z * b.w;
            acc[3][0] += a.w * b.x; acc[3][1] += a.w * b.y; acc[3][2] += a.w * b.z; acc[3][3] += a.w * b.w;
        }
        __syncthreads();
    }

    float4 bb = *(const float4*)(bias + tx * 4);
    float bias4[4] = {bb.x, bb.y, bb.z, bb.w};
#pragma unroll
    for (int i = 0; i < 4; i++) {
        int gr = m0 + ty * 4 + i;
        if (gr < M) {
            float4 v;
            v.x = actf(acc[i][0] + bias4[0], act);
            v.y = actf(acc[i][1] + bias4[1], act);
            v.z = actf(acc[i][2] + bias4[2], act);
            v.w = actf(acc[i][3] + bias4[3], act);
            *(float4*)(C + (size_t)gr * ldc + tx * 4) = v;
        }
    }
}

// ---------------- kernels ----------------------------------------------------

// des / tweet projection: [NN,768] x [768,64] -> g_xA[:, coloff..coloff+63], lrelu
__global__ void k_proj768(const float* __restrict__ A,
                          const float* __restrict__ W,
                          const float* __restrict__ bias,
                          int coloff)
{
    gemm_tile(A, DESW, W, 64, bias, g_xA + coloff, HD, NN, DESW, blockIdx.x * 64, 1);
}

// num_prop / cat_prop projection (tiny K): one thread per (n, j)
__global__ void k_projsmall(const float* __restrict__ A, int K,
                            const float* __restrict__ W,
                            const float* __restrict__ bias,
                            int coloff)
{
    int id = blockIdx.x * blockDim.x + threadIdx.x;
    if (id >= NN * 64) return;
    int n = id >> 6, j = id & 63;
    float s = bias[j];
    for (int k = 0; k < K; k++) s += A[(size_t)n * K + k] * W[k * 64 + j];
    g_xA[(size_t)n * HD + coloff + j] = actf(s, 1);
}

// x = lrelu(g_xA @ w_in + b_in) -> g_xB      grid (ceil(NN/64), 4)
__global__ void k_gemm_hid(const float* __restrict__ W,
                           const float* __restrict__ bias)
{
    int cb = blockIdx.y * 64;
    gemm_tile(g_xA, HD, W + cb, HD, bias + cb, g_xB + cb, HD, NN, HD,
              blockIdx.x * 64, 1);
}

// fused RGCN T-stage: X @ [w_r0 | w_r1 | root] + bias, relu -> g_h
// grid (ceil(NN/64), 12): blockIdx.y selects 64-col tile across the 768 cols
__global__ void k_gemm_rgcn(const float* __restrict__ w,
                            const float* __restrict__ root,
                            const float* __restrict__ bias,
                            int inSel)
{
    const float* X = inSel ? g_xB : g_xA;
    int by  = blockIdx.y;
    int seg = by >> 2;            // 0,1 -> relations, 2 -> root
    int lc  = (by & 3) * 64;      // local col within [0,256)
    const float* B = (seg < 2 ? w + (size_t)seg * HD * HD : root) + lc;
    float* C = g_h + ((size_t)seg * NN) * HD + lc;
    gemm_tile(X, HD, B, HD, bias + lc, C, HD, NN, HD, blockIdx.x * 64, 2);
}

__global__ void k_zero_agg() {
    size_t id = (size_t)blockIdx.x * blockDim.x + threadIdx.x;
    size_t n4 = (size_t)2 * NN * HD / 4;
    if (id < n4) ((float4*)g_agg)[id] = make_float4(0.f, 0.f, 0.f, 0.f);
}

__global__ void k_zero_cnt() {
    int id = blockIdx.x * blockDim.x + threadIdx.x;
    if (id < 2 * NN) g_cnt[id] = 0;
}

__global__ void k_count(const int* __restrict__ dst, const int* __restrict__ et) {
    int e = blockIdx.x * blockDim.x + threadIdx.x;
    if (e >= EE) return;
    atomicAdd(&g_cnt[et[e] * NN + dst[e]], 1);
}

__global__ void k_inv() {
    int id = blockIdx.x * blockDim.x + threadIdx.x;
    if (id >= 2 * NN) return;
    int c = g_cnt[id];
    g_dinv[id] = 1.f / (float)(c > 0 ? c : 1);
}

// one warp per edge: gather h_rel row at src, atomically accumulate at (rel,dst)
__global__ void k_scatter(const int* __restrict__ src,
                          const int* __restrict__ dst,
                          const int* __restrict__ et)
{
    int g = blockIdx.x * blockDim.x + threadIdx.x;
    int e = g >> 5, lane = g & 31;
    if (e >= EE) return;
    int r = et[e], s = src[e], d = dst[e];
    const float4* in = (const float4*)(g_h + ((size_t)r * NN + s) * HD);
    float* op = g_agg + ((size_t)r * NN + d) * HD;
    float4 v0 = in[lane];
    float4 v1 = in[lane + 32];
    float* p = op + lane * 4;
    atomicAdd(p + 0, v0.x); atomicAdd(p + 1, v0.y);
    atomicAdd(p + 2, v0.z); atomicAdd(p + 3, v0.w);
    float* q = op + 128 + lane * 4;
    atomicAdd(q + 0, v1.x); atomicAdd(q + 1, v1.y);
    atomicAdd(q + 2, v1.z); atomicAdd(q + 3, v1.w);
}

// x_out = h_root + agg0 * dinv0 + agg1 * dinv1
__global__ void k_combine(int outSel) {
    int id = blockIdx.x * blockDim.x + threadIdx.x;
    if (id >= NN * 64) return;
    int n = id >> 6, q = id & 63;
    float* xout = outSel ? g_xB : g_xA;
    const float4* hr = (const float4*)(g_h + ((size_t)2 * NN + n) * HD);
    const float4* a0 = (const float4*)(g_agg + (size_t)n * HD);
    const float4* a1 = (const float4*)(g_agg + ((size_t)NN + n) * HD);
    float i0 = g_dinv[n], i1 = g_dinv[NN + n];
    float4 h4 = hr[q], x0 = a0[q], x1 = a1[q];
    float4 o;
    o.x = h4.x + x0.x * i0 + x1.x * i1;
    o.y = h4.y + x0.y * i0 + x1.y * i1;
    o.z = h4.z + x0.z * i0 + x1.z * i1;
    o.w = h4.w + x0.w * i0 + x1.w * i1;
    ((float4*)(xout + (size_t)n * HD))[q] = o;
}

// head: logits = g_xB @ w_out[256,2] + b_out   (one warp per row)
__global__ void k_out(const float* __restrict__ W,
                      const float* __restrict__ b,
                      float* __restrict__ out)
{
    int g = blockIdx.x * blockDim.x + threadIdx.x;
    int n = g >> 5, lane = g & 31;
    if (n >= NN) return;
    const float* xr = g_xB + (size_t)n * HD;
    float s0 = 0.f, s1 = 0.f;
#pragma unroll
    for (int j = lane; j < HD; j += 32) {
        float v = xr[j];
        float2 w = *(const float2*)(W + j * 2);
        s0 += v * w.x;
        s1 += v * w.y;
    }
#pragma unroll
    for (int o = 16; o; o >>= 1) {
        s0 += __shfl_down_sync(0xFFFFFFFFu, s0, o);
        s1 += __shfl_down_sync(0xFFFFFFFFu, s1, o);
    }
    if (lane == 0) {
        out[(size_t)n * 2 + 0] = s0 + b[0];
        out[(size_t)n * 2 + 1] = s1 + b[1];
    }
}

// ---------------- launch ------------------------------------------------------
extern "C" void kernel_launch(void* const* d_in, const int* in_sizes, int n_in,
                              void* d_out, int out_size)
{
    const float* des   = (const float*)d_in[0];
    const float* tweet = (const float*)d_in[1];
    const float* nump  = (const float*)d_in[2];
    const float* catp  = (const float*)d_in[3];
    const int*   ei    = (const int*)d_in[4];
    const int*   et    = (const int*)d_in[5];
    const float* w_des = (const float*)d_in[6];
    const float* b_des = (const float*)d_in[7];
    const float* w_tw  = (const float*)d_in[8];
    const float* b_tw  = (const float*)d_in[9];
    const float* w_num = (const float*)d_in[10];
    const float* b_num = (const float*)d_in[11];
    const float* w_cat = (const float*)d_in[12];
    const float* b_cat = (const float*)d_in[13];
    const float* w_in  = (const float*)d_in[14];
    const float* b_in  = (const float*)d_in[15];
    const float* wt1   = (const float*)d_in[16];
    const float* rt1   = (const float*)d_in[17];
    const float* bs1   = (const float*)d_in[18];
    const float* wt2   = (const float*)d_in[19];
    const float* rt2   = (const float*)d_in[20];
    const float* bs2   = (const float*)d_in[21];
    const float* w_out = (const float*)d_in[22];
    const float* b_out = (const float*)d_in[23];
    float* out = (float*)d_out;

    const int* src = ei;
    const int* dst = ei + EE;

    const int MB = (NN + 63) / 64;   // 782 row tiles

    // feature projections -> g_xA
    k_proj768<<<MB, 256>>>(des, w_des, b_des, 0);
    k_proj768<<<MB, 256>>>(tweet, w_tw, b_tw, 64);
    {
        int th = NN * 64, bl = (th + 255) / 256;
        k_projsmall<<<bl, 256>>>(nump, 5, w_num, b_num, 128);
        k_projsmall<<<bl, 256>>>(catp, 3, w_cat, b_cat, 192);
    }

    // x = lrelu(xA @ w_in + b_in) -> g_xB
    k_gemm_hid<<<dim3(MB, 4), 256>>>(w_in, b_in);

    // degree counts (shared by both layers)
    k_zero_cnt<<<(2 * NN + 255) / 256, 256>>>();
    k_count<<<(EE + 255) / 256, 256>>>(dst, et);
    k_inv<<<(2 * NN + 255) / 256, 256>>>();

    size_t agg4 = (size_t)2 * NN * HD / 4;
    int aggBl = (int)((agg4 + 255) / 256);
    int scBl = (EE * 32 + 255) / 256;
    int cmBl = (NN * 64 + 255) / 256;

    // RGCN layer 1: in g_xB -> out g_xA
    k_gemm_rgcn<<<dim3(MB, 12), 256>>>(wt1, rt1, bs1, 1);
    k_zero_agg<<<aggBl, 256>>>();
    k_scatter<<<scBl, 256>>>(src, dst, et);
    k_combine<<<cmBl, 256>>>(0);

    // RGCN layer 2: in g_xA -> out g_xB
    k_gemm_rgcn<<<dim3(MB, 12), 256>>>(wt2, rt2, bs2, 0);
    k_zero_agg<<<aggBl, 256>>>();
    k_scatter<<<scBl, 256>>>(src, dst, et);
    k_combine<<<cmBl, 256>>>(1);

    // head
    k_out<<<(NN * 32 + 255) / 256, 256>>>(w_out, b_out, out);
}

// round 4
// speedup vs baseline: 1.2661x; 1.2661x over previous
#include <cuda_runtime.h>
#include <cuda_bf16.h>
#include <cstdint>

#define NN 50000
#define EE 800000
#define HD 256
#define DESW 768

// ---------------- scratch (device globals; no runtime alloc) ----------------
__device__ __align__(16) float g_xA[(size_t)NN * HD];
__device__ __align__(16) float g_xB[(size_t)NN * HD];
__device__ __align__(16) float g_h[(size_t)3 * NN * HD];     // [rel0 | rel1 | root]
__device__ __align__(16) float g_agg[(size_t)2 * NN * HD];
__device__ __align__(16) float g_dinv[2 * NN];
__device__ __align__(16) int   g_cnt[2 * NN];

// transposed bf16 hi/lo weight store (B as [N,K] K-major)
#define OFF_DES 0
#define OFF_TW  49152
#define OFF_WIN 98304
#define OFF_R1  163840
#define OFF_R2  360448
__device__ __align__(16) __nv_bfloat16 g_whi[557056];
__device__ __align__(16) __nv_bfloat16 g_wlo[557056];

// ---------------- helpers -----------------------------------------------------
__device__ __forceinline__ uint32_t smem_u32(const void* p) {
    uint32_t a;
    asm("{ .reg .u64 t; cvta.to.shared.u64 t, %1; cvt.u32.u64 %0, t; }" : "=r"(a) : "l"(p));
    return a;
}
__device__ __forceinline__ void ldsm4(uint32_t* r, uint32_t addr) {
    asm volatile("ldmatrix.sync.aligned.m8n8.x4.shared.b16 {%0,%1,%2,%3}, [%4];"
                 : "=r"(r[0]), "=r"(r[1]), "=r"(r[2]), "=r"(r[3]) : "r"(addr));
}
__device__ __forceinline__ void mma_bf16(float* c, const uint32_t* a, const uint32_t* b) {
    asm volatile(
        "mma.sync.aligned.m16n8k16.row.col.f32.bf16.bf16.f32 "
        "{%0,%1,%2,%3}, {%4,%5,%6,%7}, {%8,%9}, {%0,%1,%2,%3};"
        : "+f"(c[0]), "+f"(c[1]), "+f"(c[2]), "+f"(c[3])
        : "r"(a[0]), "r"(a[1]), "r"(a[2]), "r"(a[3]), "r"(b[0]), "r"(b[1]));
}
__device__ __forceinline__ float actf(float v, int act) {
    if (act == 1) return v > 0.f ? v : 0.01f * v;
    if (act == 2) return v > 0.f ? v : 0.f;
    return v;
}
// 8 fp32 -> 8 bf16 hi + 8 bf16 lo, packed as uint4
__device__ __forceinline__ void cvt8(float4 x, float4 y, uint4& h, uint4& l) {
    float v[8] = {x.x, x.y, x.z, x.w, y.x, y.y, y.z, y.w};
    uint32_t hb[8], lb[8];
#pragma unroll
    for (int i = 0; i < 8; i++) {
        __nv_bfloat16 hh = __float2bfloat16_rn(v[i]);
        hb[i] = (uint32_t)__bfloat16_as_ushort(hh);
        float r = v[i] - __bfloat162float(hh);
        lb[i] = (uint32_t)__bfloat16_as_ushort(__float2bfloat16_rn(r));
    }
    h.x = hb[0] | (hb[1] << 16); h.y = hb[2] | (hb[3] << 16);
    h.z = hb[4] | (hb[5] << 16); h.w = hb[6] | (hb[7] << 16);
    l.x = lb[0] | (lb[1] << 16); l.y = lb[2] | (lb[3] << 16);
    l.z = lb[4] | (lb[5] << 16); l.w = lb[6] | (lb[7] << 16);
}

// ---------------- weight prep: W[K,N] fp32 -> g_whi/g_wlo[outOff + n*K + k] --
__global__ void k_wprep(const float* __restrict__ W, int K, int N, int outOff) {
    int id = blockIdx.x * blockDim.x + threadIdx.x;
    if (id >= K * N) return;
    int k = id / N, n = id - k * N;
    float w = W[id];
    __nv_bfloat16 h = __float2bfloat16_rn(w);
    float lo = w - __bfloat162float(h);
    g_whi[(size_t)outOff + (size_t)n * K + k] = h;
    g_wlo[(size_t)outOff + (size_t)n * K + k] = __float2bfloat16_rn(lo);
}

// ---------------- mma.sync bf16-split GEMM ------------------------------------
// C = act(A[M,K] @ B[K,*] + bias); B transposed [N,K] bf16 hi/lo at g_whi/g_wlo+bOff.
// CTA tile 128 x BN, BK=64 chunks. 8 warps: 4(m) x 2(n); warp tile 32 x BN/2.
// cmode 0: C[gr*ldc + cbase + gcol]; cmode 1: seg split into g_h (seg=gcol>>8).
template <int BN>
__global__ void __launch_bounds__(256) k_gemm_mma(
    const float* __restrict__ Aparam, int aSel, int K, int M, int bOff,
    const float* __restrict__ bias, int cSel, int cbase, int ldc, int cmode, int act)
{
    extern __shared__ char sm[];
    constexpr int STR = 144;                 // padded row stride bytes (72 halves)
    constexpr int ASZ = 128 * STR;           // 18432
    constexpr int BSZ = BN * STR;
    constexpr int OA_HI = 0, OA_LO = ASZ, OB_HI = 2 * ASZ, OB_LO = 2 * ASZ + BSZ;
    constexpr int NT = BN / 16;              // n-tiles per warp (8 or 4)

    const uint32_t smb = smem_u32(sm);
    const int tid = threadIdx.x;
    const int lane = tid & 31, wid = tid >> 5;
    const int m_base = (wid & 3) * 32;
    const int n_base = (wid >> 2) * (BN / 2);

    const float* A = (aSel == 1) ? g_xA : (aSel == 2) ? g_xB : Aparam;
    const __nv_bfloat16* Bhi = g_whi + bOff;
    const __nv_bfloat16* Blo = g_wlo + bOff;

    const int m0 = blockIdx.x * 128;
    const int n0 = blockIdx.y * BN;
    const int nch = K >> 6;

    const int lrow = tid >> 1, lhalf = tid & 1;   // loader mapping

    float acc[2][NT][4];
#pragma unroll
    for (int i = 0; i < 2; i++)
#pragma unroll
        for (int j = 0; j < NT; j++)
#pragma unroll
            for (int q = 0; q < 4; q++) acc[i][j][q] = 0.f;

    // precomputed ldmatrix lane offsets
    const uint32_t aoff = (uint32_t)(m_base + (lane & 15)) * STR + (uint32_t)(lane >> 4) * 16;
    const uint32_t boff = (uint32_t)(n_base + ((lane >> 4) & 1) * 8 + (lane & 7)) * STR +
                          (uint32_t)((lane >> 3) & 1) * 16;

    for (int c = 0; c < nch; c++) {
        if (c) __syncthreads();
        const int k0 = c * 64;
        // ---- stage A: 128 x 64 fp32 -> bf16 hi/lo ----
        {
            int gr = m0 + lrow;
            uint4 h[4], l[4];
            if (gr < M) {
                const float4* srcp = (const float4*)(A + (size_t)gr * K + k0 + lhalf * 32);
#pragma unroll
                for (int j = 0; j < 4; j++) cvt8(srcp[2 * j], srcp[2 * j + 1], h[j], l[j]);
            } else {
#pragma unroll
                for (int j = 0; j < 4; j++) { h[j] = make_uint4(0,0,0,0); l[j] = make_uint4(0,0,0,0); }
            }
#pragma unroll
            for (int j = 0; j < 4; j++) {
                uint32_t off = lrow * STR + lhalf * 64 + j * 16;
                *(uint4*)(sm + OA_HI + off) = h[j];
                *(uint4*)(sm + OA_LO + off) = l[j];
            }
        }
        // ---- stage B: BN x 64 bf16 hi/lo (pre-transposed in global) ----
        if (lrow < BN) {
            const uint4* sh = (const uint4*)(Bhi + (size_t)(n0 + lrow) * K + k0 + lhalf * 32);
            const uint4* sl = (const uint4*)(Blo + (size_t)(n0 + lrow) * K + k0 + lhalf * 32);
#pragma unroll
            for (int j = 0; j < 4; j++) {
                uint32_t off = lrow * STR + lhalf * 64 + j * 16;
                *(uint4*)(sm + OB_HI + off) = sh[j];
                *(uint4*)(sm + OB_LO + off) = sl[j];
            }
        }
        __syncthreads();

        // ---- compute: 4 k16 steps, 3 split terms ----
#pragma unroll
        for (int k16 = 0; k16 < 4; k16++) {
            uint32_t aH[2][4], aL[2][4];
#pragma unroll
            for (int mi = 0; mi < 2; mi++) {
                uint32_t ad = smb + aoff + mi * (16 * STR) + k16 * 32;
                ldsm4(aH[mi], ad + OA_HI);
                ldsm4(aL[mi], ad + OA_LO);
            }
#pragma unroll
            for (int pr = 0; pr < NT / 2; pr++) {
                uint32_t bH[4], bL[4];
                uint32_t bd = smb + boff + pr * (16 * STR) + k16 * 32;
                ldsm4(bH, bd + OB_HI);
                ldsm4(bL, bd + OB_LO);
#pragma unroll
                for (int mi = 0; mi < 2; mi++)
#pragma unroll
                    for (int t = 0; t < 2; t++) {
                        int nt = pr * 2 + t;
                        mma_bf16(acc[mi][nt], aH[mi], bH + 2 * t);
                        mma_bf16(acc[mi][nt], aH[mi], bL + 2 * t);
                        mma_bf16(acc[mi][nt], aL[mi], bH + 2 * t);
                    }
            }
        }
    }

    // ---- epilogue: bias + act + store ----
    float* Cb = (cSel == 1) ? g_xA : (cSel == 2) ? g_xB : g_h;
#pragma unroll
    for (int mi = 0; mi < 2; mi++) {
#pragma unroll
        for (int nt = 0; nt < NT; nt++) {
            int colL = n_base + nt * 8 + (lane & 3) * 2;
            int gcolL = n0 + colL;
            int bidx = (cmode == 1) ? (gcolL & 255) : (cbase + gcolL);
            float b0 = bias[bidx], b1 = bias[bidx + 1];
#pragma unroll
            for (int half = 0; half < 2; half++) {
                int gr = m0 + m_base + mi * 16 + (lane >> 2) + half * 8;
                if (gr < M) {
                    float2 v;
                    v.x = actf(acc[mi][nt][half * 2 + 0] + b0, act);
                    v.y = actf(acc[mi][nt][half * 2 + 1] + b1, act);
                    float* cp;
                    if (cmode == 1) {
                        int seg = gcolL >> 8, lc = gcolL & 255;
                        cp = Cb + ((size_t)seg * M + gr) * 256 + lc;
                    } else {
                        cp = Cb + (size_t)gr * ldc + cbase + gcolL;
                    }
                    *(float2*)cp = v;
                }
            }
        }
    }
}

// ---------------- small projection (K=5/3) -----------------------------------
__global__ void k_projsmall(const float* __restrict__ A, int K,
                            const float* __restrict__ W,
                            const float* __restrict__ bias, int coloff)
{
    int id = blockIdx.x * blockDim.x + threadIdx.x;
    if (id >= NN * 64) return;
    int n = id >> 6, j = id & 63;
    float s = bias[j];
    for (int k = 0; k < K; k++) s += A[(size_t)n * K + k] * W[k * 64 + j];
    g_xA[(size_t)n * HD + coloff + j] = actf(s, 1);
}

// ---------------- edge stage --------------------------------------------------
__global__ void k_zero_agg() {
    size_t id = (size_t)blockIdx.x * blockDim.x + threadIdx.x;
    size_t n4 = (size_t)2 * NN * HD / 4;
    if (id < n4) ((float4*)g_agg)[id] = make_float4(0.f, 0.f, 0.f, 0.f);
}
__global__ void k_zero_cnt() {
    int id = blockIdx.x * blockDim.x + threadIdx.x;
    if (id < 2 * NN) g_cnt[id] = 0;
}
__global__ void k_count(const int* __restrict__ dst, const int* __restrict__ et) {
    int e = blockIdx.x * blockDim.x + threadIdx.x;
    if (e >= EE) return;
    atomicAdd(&g_cnt[et[e] * NN + dst[e]], 1);
}
__global__ void k_inv() {
    int id = blockIdx.x * blockDim.x + threadIdx.x;
    if (id >= 2 * NN) return;
    int c = g_cnt[id];
    g_dinv[id] = 1.f / (float)(c > 0 ? c : 1);
}
__global__ void k_scatter(const int* __restrict__ src,
                          const int* __restrict__ dst,
                          const int* __restrict__ et)
{
    int g = blockIdx.x * blockDim.x + threadIdx.x;
    int e = g >> 5, lane = g & 31;
    if (e >= EE) return;
    int r = et[e], s = src[e], d = dst[e];
    const float4* in = (const float4*)(g_h + ((size_t)r * NN + s) * HD);
    float* op = g_agg + ((size_t)r * NN + d) * HD;
    float4 v0 = in[lane];
    float4 v1 = in[lane + 32];
    float* p = op + lane * 4;
    atomicAdd(p + 0, v0.x); atomicAdd(p + 1, v0.y);
    atomicAdd(p + 2, v0.z); atomicAdd(p + 3, v0.w);
    float* q = op + 128 + lane * 4;
    atomicAdd(q + 0, v1.x); atomicAdd(q + 1, v1.y);
    atomicAdd(q + 2, v1.z); atomicAdd(q + 3, v1.w);
}
__global__ void k_combine(int outSel) {
    int id = blockIdx.x * blockDim.x + threadIdx.x;
    if (id >= NN * 64) return;
    int n = id >> 6, q = id & 63;
    float* xout = outSel ? g_xB : g_xA;
    const float4* hr = (const float4*)(g_h + ((size_t)2 * NN + n) * HD);
    const float4* a0 = (const float4*)(g_agg + (size_t)n * HD);
    const float4* a1 = (const float4*)(g_agg + ((size_t)NN + n) * HD);
    float i0 = g_dinv[n], i1 = g_dinv[NN + n];
    float4 h4 = hr[q], x0 = a0[q], x1 = a1[q];
    float4 o;
    o.x = h4.x + x0.x * i0 + x1.x * i1;
    o.y = h4.y + x0.y * i0 + x1.y * i1;
    o.z = h4.z + x0.z * i0 + x1.z * i1;
    o.w = h4.w + x0.w * i0 + x1.w * i1;
    ((float4*)(xout + (size_t)n * HD))[q] = o;
}

// ---------------- head --------------------------------------------------------
__global__ void k_out(const float* __restrict__ W,
                      const float* __restrict__ b,
                      float* __restrict__ out)
{
    int g = blockIdx.x * blockDim.x + threadIdx.x;
    int n = g >> 5, lane = g & 31;
    if (n >= NN) return;
    const float* xr = g_xB + (size_t)n * HD;
    float s0 = 0.f, s1 = 0.f;
#pragma unroll
    for (int j = lane; j < HD; j += 32) {
        float v = xr[j];
        float2 w = *(const float2*)(W + j * 2);
        s0 += v * w.x;
        s1 += v * w.y;
    }
#pragma unroll
    for (int o = 16; o; o >>= 1) {
        s0 += __shfl_down_sync(0xFFFFFFFFu, s0, o);
        s1 += __shfl_down_sync(0xFFFFFFFFu, s1, o);
    }
    if (lane == 0) {
        out[(size_t)n * 2 + 0] = s0 + b[0];
        out[(size_t)n * 2 + 1] = s1 + b[1];
    }
}

// ---------------- launch ------------------------------------------------------
extern "C" void kernel_launch(void* const* d_in, const int* in_sizes, int n_in,
                              void* d_out, int out_size)
{
    const float* des   = (const float*)d_in[0];
    const float* tweet = (const float*)d_in[1];
    const float* nump  = (const float*)d_in[2];
    const float* catp  = (const float*)d_in[3];
    const int*   ei    = (const int*)d_in[4];
    const int*   et    = (const int*)d_in[5];
    const float* w_des = (const float*)d_in[6];
    const float* b_des = (const float*)d_in[7];
    const float* w_tw  = (const float*)d_in[8];
    const float* b_tw  = (const float*)d_in[9];
    const float* w_num = (const float*)d_in[10];
    const float* b_num = (const float*)d_in[11];
    const float* w_cat = (const float*)d_in[12];
    const float* b_cat = (const float*)d_in[13];
    const float* w_in  = (const float*)d_in[14];
    const float* b_in  = (const float*)d_in[15];
    const float* wt1   = (const float*)d_in[16];
    const float* rt1   = (const float*)d_in[17];
    const float* bs1   = (const float*)d_in[18];
    const float* wt2   = (const float*)d_in[19];
    const float* rt2   = (const float*)d_in[20];
    const float* bs2   = (const float*)d_in[21];
    const float* w_out = (const float*)d_in[22];
    const float* b_out = (const float*)d_in[23];
    float* out = (float*)d_out;

    const int* src = ei;
    const int* dst = ei + EE;

    const int SZ128 = 4 * 18432;                    // 73728
    const int SZ64  = 2 * 18432 + 2 * 9216;         // 55296
    cudaFuncSetAttribute(k_gemm_mma<128>, cudaFuncAttributeMaxDynamicSharedMemorySize, SZ128);
    cudaFuncSetAttribute(k_gemm_mma<64>,  cudaFuncAttributeMaxDynamicSharedMemorySize, SZ64);

    // weight prep (transpose + bf16 hi/lo split)
    k_wprep<<<(768 * 64 + 255) / 256, 256>>>(w_des, 768, 64, OFF_DES);
    k_wprep<<<(768 * 64 + 255) / 256, 256>>>(w_tw, 768, 64, OFF_TW);
    k_wprep<<<(256 * 256 + 255) / 256, 256>>>(w_in, 256, 256, OFF_WIN);
    k_wprep<<<(256 * 256 + 255) / 256, 256>>>(wt1, 256, 256, OFF_R1);
    k_wprep<<<(256 * 256 + 255) / 256, 256>>>(wt1 + 65536, 256, 256, OFF_R1 + 65536);
    k_wprep<<<(256 * 256 + 255) / 256, 256>>>(rt1, 256, 256, OFF_R1 + 131072);
    k_wprep<<<(256 * 256 + 255) / 256, 256>>>(wt2, 256, 256, OFF_R2);
    k_wprep<<<(256 * 256 + 255) / 256, 256>>>(wt2 + 65536, 256, 256, OFF_R2 + 65536);
    k_wprep<<<(256 * 256 + 255) / 256, 256>>>(rt2, 256, 256, OFF_R2 + 131072);

    const int MB = (NN + 127) / 128;  // 391 row tiles

    // feature projections -> g_xA
    k_gemm_mma<64><<<dim3(MB, 1), 256, SZ64>>>(des, 0, 768, NN, OFF_DES, b_des, 1, 0, HD, 0, 1);
    k_gemm_mma<64><<<dim3(MB, 1), 256, SZ64>>>(tweet, 0, 768, NN, OFF_TW, b_tw, 1, 64, HD, 0, 1);
    {
        int th = NN * 64, bl = (th + 255) / 256;
        k_projsmall<<<bl, 256>>>(nump, 5, w_num, b_num, 128);
        k_projsmall<<<bl, 256>>>(catp, 3, w_cat, b_cat, 192);
    }

    // x = lrelu(xA @ w_in + b_in) -> g_xB
    k_gemm_mma<128><<<dim3(MB, 2), 256, SZ128>>>(nullptr, 1, 256, NN, OFF_WIN, b_in, 2, 0, HD, 0, 1);

    // degree counts (shared by both layers)
    k_zero_cnt<<<(2 * NN + 255) / 256, 256>>>();
    k_count<<<(EE + 255) / 256, 256>>>(dst, et);
    k_inv<<<(2 * NN + 255) / 256, 256>>>();

    size_t agg4 = (size_t)2 * NN * HD / 4;
    int aggBl = (int)((agg4 + 255) / 256);
    int scBl = (EE * 32 + 255) / 256;
    int cmBl = (NN * 64 + 255) / 256;

    // RGCN layer 1: in g_xB -> out g_xA
    k_gemm_mma<128><<<dim3(MB, 6), 256, SZ128>>>(nullptr, 2, 256, NN, OFF_R1, bs1, 3, 0, HD, 1, 2);
    k_zero_agg<<<aggBl, 256>>>();
    k_scatter<<<scBl, 256>>>(src, dst, et);
    k_combine<<<cmBl, 256>>>(0);

    // RGCN layer 2: in g_xA -> out g_xB
    k_gemm_mma<128><<<dim3(MB, 6), 256, SZ128>>>(nullptr, 1, 256, NN, OFF_R2, bs2, 3, 0, HD, 1, 2);
    k_zero_agg<<<aggBl, 256>>>();
    k_scatter<<<scBl, 256>>>(src, dst, et);
    k_combine<<<cmBl, 256>>>(1);

    // head
    k_out<<<(NN * 32 + 255) / 256, 256>>>(w_out, b_out, out);
}

// round 5
// speedup vs baseline: 1.7296x; 1.3661x over previous
#include <cuda_runtime.h>
#include <cuda_bf16.h>
#include <cstdint>

#define NN 50000
#define EE 800000
#define HD 256
#define DESW 768

// ---------------- scratch (device globals; no runtime alloc) ----------------
__device__ __align__(16) float g_xA[(size_t)NN * HD];
__device__ __align__(16) float g_xB[(size_t)NN * HD];
__device__ __align__(16) float g_h[(size_t)3 * NN * HD];     // [rel0 | rel1 | root]
__device__ __align__(16) float g_agg[(size_t)2 * NN * HD];
__device__ __align__(16) float g_dinv[2 * NN];
__device__ __align__(16) int   g_cnt[2 * NN];

// transposed bf16 hi/lo weight store (B as [N,K] K-major)
#define OFF_DES 0
#define OFF_TW  49152
#define OFF_WIN 98304
#define OFF_R1  163840
#define OFF_R2  360448
__device__ __align__(16) __nv_bfloat16 g_whi[557056];
__device__ __align__(16) __nv_bfloat16 g_wlo[557056];

// ---------------- helpers -----------------------------------------------------
__device__ __forceinline__ uint32_t smem_u32(const void* p) {
    uint32_t a;
    asm("{ .reg .u64 t; cvta.to.shared.u64 t, %1; cvt.u32.u64 %0, t; }" : "=r"(a) : "l"(p));
    return a;
}
__device__ __forceinline__ void ldsm4(uint32_t* r, uint32_t addr) {
    asm volatile("ldmatrix.sync.aligned.m8n8.x4.shared.b16 {%0,%1,%2,%3}, [%4];"
                 : "=r"(r[0]), "=r"(r[1]), "=r"(r[2]), "=r"(r[3]) : "r"(addr));
}
__device__ __forceinline__ void mma_bf16(float* c, const uint32_t* a, const uint32_t* b) {
    asm volatile(
        "mma.sync.aligned.m16n8k16.row.col.f32.bf16.bf16.f32 "
        "{%0,%1,%2,%3}, {%4,%5,%6,%7}, {%8,%9}, {%0,%1,%2,%3};"
        : "+f"(c[0]), "+f"(c[1]), "+f"(c[2]), "+f"(c[3])
        : "r"(a[0]), "r"(a[1]), "r"(a[2]), "r"(a[3]), "r"(b[0]), "r"(b[1]));
}
__device__ __forceinline__ void red_add_v4(float* p, float4 v) {
    asm volatile("red.global.add.v4.f32 [%0], {%1,%2,%3,%4};"
                 :: "l"(p), "f"(v.x), "f"(v.y), "f"(v.z), "f"(v.w) : "memory");
}
__device__ __forceinline__ float actf(float v, int act) {
    if (act == 1) return v > 0.f ? v : 0.01f * v;
    if (act == 2) return v > 0.f ? v : 0.f;
    return v;
}
// 8 fp32 -> 8 bf16 hi + 8 bf16 lo, packed as uint4
__device__ __forceinline__ void cvt8(float4 x, float4 y, uint4& h, uint4& l) {
    float v[8] = {x.x, x.y, x.z, x.w, y.x, y.y, y.z, y.w};
    uint32_t hb[8], lb[8];
#pragma unroll
    for (int i = 0; i < 8; i++) {
        __nv_bfloat16 hh = __float2bfloat16_rn(v[i]);
        hb[i] = (uint32_t)__bfloat16_as_ushort(hh);
        float r = v[i] - __bfloat162float(hh);
        lb[i] = (uint32_t)__bfloat16_as_ushort(__float2bfloat16_rn(r));
    }
    h.x = hb[0] | (hb[1] << 16); h.y = hb[2] | (hb[3] << 16);
    h.z = hb[4] | (hb[5] << 16); h.w = hb[6] | (hb[7] << 16);
    l.x = lb[0] | (lb[1] << 16); l.y = lb[2] | (lb[3] << 16);
    l.z = lb[4] | (lb[5] << 16); l.w = lb[6] | (lb[7] << 16);
}

// ---------------- weight prep: W[K,N] fp32 -> g_whi/g_wlo[outOff + n*K + k] --
__global__ void k_wprep(const float* __restrict__ W, int K, int N, int outOff) {
    int id = blockIdx.x * blockDim.x + threadIdx.x;
    if (id >= K * N) return;
    int k = id / N, n = id - k * N;
    float w = W[id];
    __nv_bfloat16 h = __float2bfloat16_rn(w);
    float lo = w - __bfloat162float(h);
    g_whi[(size_t)outOff + (size_t)n * K + k] = h;
    g_wlo[(size_t)outOff + (size_t)n * K + k] = __float2bfloat16_rn(lo);
}

// ---------------- mma.sync bf16-split GEMM ------------------------------------
// C = act(A[M,K] @ B[K,*] + bias); B transposed [N,K] bf16 hi/lo at g_whi/g_wlo+bOff.
// CTA tile 128 x BN, BK=64 chunks. 8 warps: 4(m) x 2(n); warp tile 32 x BN/2.
// Grid: x = column tile (adjacent CTAs share A row tile -> L2 reuse), y = row tile.
// cmode 0: C[gr*ldc + cbase + gcol]; cmode 1: seg split into g_h (seg=gcol>>8).
template <int BN>
__global__ void __launch_bounds__(256) k_gemm_mma(
    const float* __restrict__ Aparam, int aSel, int K, int M, int bOff,
    const float* __restrict__ bias, int cSel, int cbase, int ldc, int cmode, int act)
{
    extern __shared__ char sm[];
    constexpr int STR = 144;                 // padded row stride bytes (72 halves)
    constexpr int ASZ = 128 * STR;           // 18432
    constexpr int BSZ = BN * STR;
    constexpr int OA_HI = 0, OA_LO = ASZ, OB_HI = 2 * ASZ, OB_LO = 2 * ASZ + BSZ;
    constexpr int NT = BN / 16;              // n-tiles per warp (8 or 4)

    const uint32_t smb = smem_u32(sm);
    const int tid = threadIdx.x;
    const int lane = tid & 31, wid = tid >> 5;
    const int m_base = (wid & 3) * 32;
    const int n_base = (wid >> 2) * (BN / 2);

    const float* A = (aSel == 1) ? g_xA : (aSel == 2) ? g_xB : Aparam;
    const __nv_bfloat16* Bhi = g_whi + bOff;
    const __nv_bfloat16* Blo = g_wlo + bOff;

    const int m0 = blockIdx.y * 128;
    const int n0 = blockIdx.x * BN;
    const int nch = K >> 6;

    const int lrow = tid >> 1, lhalf = tid & 1;   // loader mapping

    float acc[2][NT][4];
#pragma unroll
    for (int i = 0; i < 2; i++)
#pragma unroll
        for (int j = 0; j < NT; j++)
#pragma unroll
            for (int q = 0; q < 4; q++) acc[i][j][q] = 0.f;

    // precomputed ldmatrix lane offsets
    const uint32_t aoff = (uint32_t)(m_base + (lane & 15)) * STR + (uint32_t)(lane >> 4) * 16;
    const uint32_t boff = (uint32_t)(n_base + ((lane >> 4) & 1) * 8 + (lane & 7)) * STR +
                          (uint32_t)((lane >> 3) & 1) * 16;

    for (int c = 0; c < nch; c++) {
        if (c) __syncthreads();
        const int k0 = c * 64;
        // ---- stage A: 128 x 64 fp32 -> bf16 hi/lo ----
        {
            int gr = m0 + lrow;
            uint4 h[4], l[4];
            if (gr < M) {
                const float4* srcp = (const float4*)(A + (size_t)gr * K + k0 + lhalf * 32);
#pragma unroll
                for (int j = 0; j < 4; j++) cvt8(srcp[2 * j], srcp[2 * j + 1], h[j], l[j]);
            } else {
#pragma unroll
                for (int j = 0; j < 4; j++) { h[j] = make_uint4(0,0,0,0); l[j] = make_uint4(0,0,0,0); }
            }
#pragma unroll
            for (int j = 0; j < 4; j++) {
                uint32_t off = lrow * STR + lhalf * 64 + j * 16;
                *(uint4*)(sm + OA_HI + off) = h[j];
                *(uint4*)(sm + OA_LO + off) = l[j];
            }
        }
        // ---- stage B: BN x 64 bf16 hi/lo (pre-transposed in global) ----
        if (lrow < BN) {
            const uint4* sh = (const uint4*)(Bhi + (size_t)(n0 + lrow) * K + k0 + lhalf * 32);
            const uint4* sl = (const uint4*)(Blo + (size_t)(n0 + lrow) * K + k0 + lhalf * 32);
#pragma unroll
            for (int j = 0; j < 4; j++) {
                uint32_t off = lrow * STR + lhalf * 64 + j * 16;
                *(uint4*)(sm + OB_HI + off) = sh[j];
                *(uint4*)(sm + OB_LO + off) = sl[j];
            }
        }
        __syncthreads();

        // ---- compute: 4 k16 steps, 3 split terms ----
#pragma unroll
        for (int k16 = 0; k16 < 4; k16++) {
            uint32_t aH[2][4], aL[2][4];
#pragma unroll
            for (int mi = 0; mi < 2; mi++) {
                uint32_t ad = smb + aoff + mi * (16 * STR) + k16 * 32;
                ldsm4(aH[mi], ad + OA_HI);
                ldsm4(aL[mi], ad + OA_LO);
            }
#pragma unroll
            for (int pr = 0; pr < NT / 2; pr++) {
                uint32_t bH[4], bL[4];
                uint32_t bd = smb + boff + pr * (16 * STR) + k16 * 32;
                ldsm4(bH, bd + OB_HI);
                ldsm4(bL, bd + OB_LO);
#pragma unroll
                for (int mi = 0; mi < 2; mi++)
#pragma unroll
                    for (int t = 0; t < 2; t++) {
                        int nt = pr * 2 + t;
                        mma_bf16(acc[mi][nt], aH[mi], bH + 2 * t);
                        mma_bf16(acc[mi][nt], aH[mi], bL + 2 * t);
                        mma_bf16(acc[mi][nt], aL[mi], bH + 2 * t);
                    }
            }
        }
    }

    // ---- epilogue: bias + act + store ----
    float* Cb = (cSel == 1) ? g_xA : (cSel == 2) ? g_xB : g_h;
#pragma unroll
    for (int mi = 0; mi < 2; mi++) {
#pragma unroll
        for (int nt = 0; nt < NT; nt++) {
            int colL = n_base + nt * 8 + (lane & 3) * 2;
            int gcolL = n0 + colL;
            int bidx = (cmode == 1) ? (gcolL & 255) : (cbase + gcolL);
            float b0 = bias[bidx], b1 = bias[bidx + 1];
#pragma unroll
            for (int half = 0; half < 2; half++) {
                int gr = m0 + m_base + mi * 16 + (lane >> 2) + half * 8;
                if (gr < M) {
                    float2 v;
                    v.x = actf(acc[mi][nt][half * 2 + 0] + b0, act);
                    v.y = actf(acc[mi][nt][half * 2 + 1] + b1, act);
                    float* cp;
                    if (cmode == 1) {
                        int seg = gcolL >> 8, lc = gcolL & 255;
                        cp = Cb + ((size_t)seg * M + gr) * 256 + lc;
                    } else {
                        cp = Cb + (size_t)gr * ldc + cbase + gcolL;
                    }
                    *(float2*)cp = v;
                }
            }
        }
    }
}

// ---------------- small projection (K=5/3) -----------------------------------
__global__ void k_projsmall(const float* __restrict__ A, int K,
                            const float* __restrict__ W,
                            const float* __restrict__ bias, int coloff)
{
    int id = blockIdx.x * blockDim.x + threadIdx.x;
    if (id >= NN * 64) return;
    int n = id >> 6, j = id & 63;
    float s = bias[j];
    for (int k = 0; k < K; k++) s += A[(size_t)n * K + k] * W[k * 64 + j];
    g_xA[(size_t)n * HD + coloff + j] = actf(s, 1);
}

// ---------------- edge stage --------------------------------------------------
__global__ void k_zero_agg() {
    size_t id = (size_t)blockIdx.x * blockDim.x + threadIdx.x;
    size_t n4 = (size_t)2 * NN * HD / 4;
    if (id < n4) ((float4*)g_agg)[id] = make_float4(0.f, 0.f, 0.f, 0.f);
}
__global__ void k_zero_cnt() {
    int id = blockIdx.x * blockDim.x + threadIdx.x;
    if (id < 2 * NN) g_cnt[id] = 0;
}
__global__ void k_count(const int* __restrict__ dst, const int* __restrict__ et) {
    int e = blockIdx.x * blockDim.x + threadIdx.x;
    if (e >= EE) return;
    atomicAdd(&g_cnt[et[e] * NN + dst[e]], 1);
}
__global__ void k_inv() {
    int id = blockIdx.x * blockDim.x + threadIdx.x;
    if (id >= 2 * NN) return;
    int c = g_cnt[id];
    g_dinv[id] = 1.f / (float)(c > 0 ? c : 1);
}
// one warp per edge: gather h_rel row at src, vectorized red.v4 accumulate at (rel,dst)
__global__ void k_scatter(const int* __restrict__ src,
                          const int* __restrict__ dst,
                          const int* __restrict__ et)
{
    int g = blockIdx.x * blockDim.x + threadIdx.x;
    int e = g >> 5, lane = g & 31;
    if (e >= EE) return;
    int r = et[e], s = src[e], d = dst[e];
    const float4* in = (const float4*)(g_h + ((size_t)r * NN + s) * HD);
    float* op = g_agg + ((size_t)r * NN + d) * HD;
    float4 v0 = in[lane];
    float4 v1 = in[lane + 32];
    red_add_v4(op + lane * 4, v0);
    red_add_v4(op + 128 + lane * 4, v1);
}
__global__ void k_combine(int outSel) {
    int id = blockIdx.x * blockDim.x + threadIdx.x;
    if (id >= NN * 64) return;
    int n = id >> 6, q = id & 63;
    float* xout = outSel ? g_xB : g_xA;
    const float4* hr = (const float4*)(g_h + ((size_t)2 * NN + n) * HD);
    const float4* a0 = (const float4*)(g_agg + (size_t)n * HD);
    const float4* a1 = (const float4*)(g_agg + ((size_t)NN + n) * HD);
    float i0 = g_dinv[n], i1 = g_dinv[NN + n];
    float4 h4 = hr[q], x0 = a0[q], x1 = a1[q];
    float4 o;
    o.x = h4.x + x0.x * i0 + x1.x * i1;
    o.y = h4.y + x0.y * i0 + x1.y * i1;
    o.z = h4.z + x0.z * i0 + x1.z * i1;
    o.w = h4.w + x0.w * i0 + x1.w * i1;
    ((float4*)(xout + (size_t)n * HD))[q] = o;
}

// ---------------- head --------------------------------------------------------
__global__ void k_out(const float* __restrict__ W,
                      const float* __restrict__ b,
                      float* __restrict__ out)
{
    int g = blockIdx.x * blockDim.x + threadIdx.x;
    int n = g >> 5, lane = g & 31;
    if (n >= NN) return;
    const float* xr = g_xB + (size_t)n * HD;
    float s0 = 0.f, s1 = 0.f;
#pragma unroll
    for (int j = lane; j < HD; j += 32) {
        float v = xr[j];
        float2 w = *(const float2*)(W + j * 2);
        s0 += v * w.x;
        s1 += v * w.y;
    }
#pragma unroll
    for (int o = 16; o; o >>= 1) {
        s0 += __shfl_down_sync(0xFFFFFFFFu, s0, o);
        s1 += __shfl_down_sync(0xFFFFFFFFu, s1, o);
    }
    if (lane == 0) {
        out[(size_t)n * 2 + 0] = s0 + b[0];
        out[(size_t)n * 2 + 1] = s1 + b[1];
    }
}

// ---------------- launch ------------------------------------------------------
extern "C" void kernel_launch(void* const* d_in, const int* in_sizes, int n_in,
                              void* d_out, int out_size)
{
    const float* des   = (const float*)d_in[0];
    const float* tweet = (const float*)d_in[1];
    const float* nump  = (const float*)d_in[2];
    const float* catp  = (const float*)d_in[3];
    const int*   ei    = (const int*)d_in[4];
    const int*   et    = (const int*)d_in[5];
    const float* w_des = (const float*)d_in[6];
    const float* b_des = (const float*)d_in[7];
    const float* w_tw  = (const float*)d_in[8];
    const float* b_tw  = (const float*)d_in[9];
    const float* w_num = (const float*)d_in[10];
    const float* b_num = (const float*)d_in[11];
    const float* w_cat = (const float*)d_in[12];
    const float* b_cat = (const float*)d_in[13];
    const float* w_in  = (const float*)d_in[14];
    const float* b_in  = (const float*)d_in[15];
    const float* wt1   = (const float*)d_in[16];
    const float* rt1   = (const float*)d_in[17];
    const float* bs1   = (const float*)d_in[18];
    const float* wt2   = (const float*)d_in[19];
    const float* rt2   = (const float*)d_in[20];
    const float* bs2   = (const float*)d_in[21];
    const float* w_out = (const float*)d_in[22];
    const float* b_out = (const float*)d_in[23];
    float* out = (float*)d_out;

    const int* src = ei;
    const int* dst = ei + EE;

    const int SZ128 = 4 * 18432;                    // 73728
    const int SZ64  = 2 * 18432 + 2 * 9216;         // 55296
    cudaFuncSetAttribute(k_gemm_mma<128>, cudaFuncAttributeMaxDynamicSharedMemorySize, SZ128);
    cudaFuncSetAttribute(k_gemm_mma<64>,  cudaFuncAttributeMaxDynamicSharedMemorySize, SZ64);

    // weight prep (transpose + bf16 hi/lo split)
    k_wprep<<<(768 * 64 + 255) / 256, 256>>>(w_des, 768, 64, OFF_DES);
    k_wprep<<<(768 * 64 + 255) / 256, 256>>>(w_tw, 768, 64, OFF_TW);
    k_wprep<<<(256 * 256 + 255) / 256, 256>>>(w_in, 256, 256, OFF_WIN);
    k_wprep<<<(256 * 256 + 255) / 256, 256>>>(wt1, 256, 256, OFF_R1);
    k_wprep<<<(256 * 256 + 255) / 256, 256>>>(wt1 + 65536, 256, 256, OFF_R1 + 65536);
    k_wprep<<<(256 * 256 + 255) / 256, 256>>>(rt1, 256, 256, OFF_R1 + 131072);
    k_wprep<<<(256 * 256 + 255) / 256, 256>>>(wt2, 256, 256, OFF_R2);
    k_wprep<<<(256 * 256 + 255) / 256, 256>>>(wt2 + 65536, 256, 256, OFF_R2 + 65536);
    k_wprep<<<(256 * 256 + 255) / 256, 256>>>(rt2, 256, 256, OFF_R2 + 131072);

    const int MB = (NN + 127) / 128;  // 391 row tiles

    // feature projections -> g_xA
    k_gemm_mma<64><<<dim3(1, MB), 256, SZ64>>>(des, 0, 768, NN, OFF_DES, b_des, 1, 0, HD, 0, 1);
    k_gemm_mma<64><<<dim3(1, MB), 256, SZ64>>>(tweet, 0, 768, NN, OFF_TW, b_tw, 1, 64, HD, 0, 1);
    {
        int th = NN * 64, bl = (th + 255) / 256;
        k_projsmall<<<bl, 256>>>(nump, 5, w_num, b_num, 128);
        k_projsmall<<<bl, 256>>>(catp, 3, w_cat, b_cat, 192);
    }

    // x = lrelu(xA @ w_in + b_in) -> g_xB
    k_gemm_mma<128><<<dim3(2, MB), 256, SZ128>>>(nullptr, 1, 256, NN, OFF_WIN, b_in, 2, 0, HD, 0, 1);

    // degree counts (shared by both layers)
    k_zero_cnt<<<(2 * NN + 255) / 256, 256>>>();
    k_count<<<(EE + 255) / 256, 256>>>(dst, et);
    k_inv<<<(2 * NN + 255) / 256, 256>>>();

    size_t agg4 = (size_t)2 * NN * HD / 4;
    int aggBl = (int)((agg4 + 255) / 256);
    int scBl = (EE * 32 + 255) / 256;
    int cmBl = (NN * 64 + 255) / 256;

    // RGCN layer 1: in g_xB -> out g_xA
    k_gemm_mma<128><<<dim3(6, MB), 256, SZ128>>>(nullptr, 2, 256, NN, OFF_R1, bs1, 3, 0, HD, 1, 2);
    k_zero_agg<<<aggBl, 256>>>();
    k_scatter<<<scBl, 256>>>(src, dst, et);
    k_combine<<<cmBl, 256>>>(0);

    // RGCN layer 2: in g_xA -> out g_xB
    k_gemm_mma<128><<<dim3(6, MB), 256, SZ128>>>(nullptr, 1, 256, NN, OFF_R2, bs2, 3, 0, HD, 1, 2);
    k_zero_agg<<<aggBl, 256>>>();
    k_scatter<<<scBl, 256>>>(src, dst, et);
    k_combine<<<cmBl, 256>>>(1);

    // head
    k_out<<<(NN * 32 + 255) / 256, 256>>>(w_out, b_out, out);
}

// round 7
// speedup vs baseline: 1.9169x; 1.1083x over previous
#include <cuda_runtime.h>
#include <cuda_bf16.h>
#include <cstdint>

#define NN 50000
#define EE 800000
#define HD 256
#define DESW 768

// ---------------- scratch (device globals; no runtime alloc) ----------------
__device__ __align__(16) float g_xA[(size_t)NN * HD];
__device__ __align__(16) float g_xB[(size_t)NN * HD];
__device__ __align__(16) float g_h[(size_t)3 * NN * HD];     // [rel0 | rel1 | root]
__device__ __align__(16) int   g_cnt[2 * NN];
__device__ __align__(16) int   g_off[2 * NN + 1];
__device__ __align__(16) int   g_cursor[2 * NN];
__device__ __align__(16) int   g_eidx[EE];

// transposed bf16 hi/lo weight store (B as [N,K] K-major)
#define OFF_DES 0
#define OFF_TW  49152
#define OFF_WIN 98304
#define OFF_R1  163840
#define OFF_R2  360448
__device__ __align__(16) __nv_bfloat16 g_whi[557056];
__device__ __align__(16) __nv_bfloat16 g_wlo[557056];

// ---------------- helpers -----------------------------------------------------
__device__ __forceinline__ uint32_t smem_u32(const void* p) {
    uint32_t a;
    asm("{ .reg .u64 t; cvta.to.shared.u64 t, %1; cvt.u32.u64 %0, t; }" : "=r"(a) : "l"(p));
    return a;
}
__device__ __forceinline__ void ldsm4(uint32_t* r, uint32_t addr) {
    asm volatile("ldmatrix.sync.aligned.m8n8.x4.shared.b16 {%0,%1,%2,%3}, [%4];"
                 : "=r"(r[0]), "=r"(r[1]), "=r"(r[2]), "=r"(r[3]) : "r"(addr));
}
__device__ __forceinline__ void mma_bf16(float* c, const uint32_t* a, const uint32_t* b) {
    asm volatile(
        "mma.sync.aligned.m16n8k16.row.col.f32.bf16.bf16.f32 "
        "{%0,%1,%2,%3}, {%4,%5,%6,%7}, {%8,%9}, {%0,%1,%2,%3};"
        : "+f"(c[0]), "+f"(c[1]), "+f"(c[2]), "+f"(c[3])
        : "r"(a[0]), "r"(a[1]), "r"(a[2]), "r"(a[3]), "r"(b[0]), "r"(b[1]));
}
__device__ __forceinline__ float actf(float v, int act) {
    if (act == 1) return v > 0.f ? v : 0.01f * v;
    if (act == 2) return v > 0.f ? v : 0.f;
    return v;
}
// 8 fp32 -> 8 bf16 hi + 8 bf16 lo, packed as uint4
__device__ __forceinline__ void cvt8(float4 x, float4 y, uint4& h, uint4& l) {
    float v[8] = {x.x, x.y, x.z, x.w, y.x, y.y, y.z, y.w};
    uint32_t hb[8], lb[8];
#pragma unroll
    for (int i = 0; i < 8; i++) {
        __nv_bfloat16 hh = __float2bfloat16_rn(v[i]);
        hb[i] = (uint32_t)__bfloat16_as_ushort(hh);
        float r = v[i] - __bfloat162float(hh);
        lb[i] = (uint32_t)__bfloat16_as_ushort(__float2bfloat16_rn(r));
    }
    h.x = hb[0] | (hb[1] << 16); h.y = hb[2] | (hb[3] << 16);
    h.z = hb[4] | (hb[5] << 16); h.w = hb[6] | (hb[7] << 16);
    l.x = lb[0] | (lb[1] << 16); l.y = lb[2] | (lb[3] << 16);
    l.z = lb[4] | (lb[5] << 16); l.w = lb[6] | (lb[7] << 16);
}

// ---------------- weight prep -------------------------------------------------
__device__ __forceinline__ void wprep_one(const float* W, int K, int N, int outOff, int id) {
    int k = id / N, n = id - k * N;
    float w = W[id];
    __nv_bfloat16 h = __float2bfloat16_rn(w);
    float lo = w - __bfloat162float(h);
    g_whi[(size_t)outOff + (size_t)n * K + k] = h;
    g_wlo[(size_t)outOff + (size_t)n * K + k] = __float2bfloat16_rn(lo);
}
__global__ void k_wprep768(const float* __restrict__ W, int outOff) {
    int id = blockIdx.x * blockDim.x + threadIdx.x;
    if (id < 768 * 64) wprep_one(W, 768, 64, outOff, id);
}
// all seven 256x256 matrices in one launch: y: 0=w_in 1,2=wt1 3=rt1 4,5=wt2 6=rt2
__global__ void k_wprep_all(const float* __restrict__ w_in, const float* __restrict__ wt1,
                            const float* __restrict__ rt1, const float* __restrict__ wt2,
                            const float* __restrict__ rt2) {
    int id = blockIdx.x * blockDim.x + threadIdx.x;
    if (id >= 256 * 256) return;
    int y = blockIdx.y;
    const float* W;
    int off;
    switch (y) {
        case 0: W = w_in;          off = OFF_WIN;           break;
        case 1: W = wt1;           off = OFF_R1;            break;
        case 2: W = wt1 + 65536;   off = OFF_R1 + 65536;    break;
        case 3: W = rt1;           off = OFF_R1 + 131072;   break;
        case 4: W = wt2;           off = OFF_R2;            break;
        case 5: W = wt2 + 65536;   off = OFF_R2 + 65536;    break;
        default: W = rt2;          off = OFF_R2 + 131072;   break;
    }
    wprep_one(W, 256, 256, off, id);
}

// ---------------- mma.sync bf16-split GEMM (R5 winner core) -------------------
template <int BN>
__global__ void __launch_bounds__(256) k_gemm_mma(
    const float* __restrict__ Aparam, int aSel, int K, int M, int bOff,
    const float* __restrict__ bias, int cSel, int cbase, int ldc, int cmode, int act)
{
    extern __shared__ char sm[];
    constexpr int STR = 144;
    constexpr int ASZ = 128 * STR;
    constexpr int BSZ = BN * STR;
    constexpr int OA_HI = 0, OA_LO = ASZ, OB_HI = 2 * ASZ, OB_LO = 2 * ASZ + BSZ;
    constexpr int NT = BN / 16;

    const uint32_t smb = smem_u32(sm);
    const int tid = threadIdx.x;
    const int lane = tid & 31, wid = tid >> 5;
    const int m_base = (wid & 3) * 32;
    const int n_base = (wid >> 2) * (BN / 2);

    const float* A = (aSel == 1) ? g_xA : (aSel == 2) ? g_xB : Aparam;
    const __nv_bfloat16* Bhi = g_whi + bOff;
    const __nv_bfloat16* Blo = g_wlo + bOff;

    const int m0 = blockIdx.y * 128;
    const int n0 = blockIdx.x * BN;
    const int nch = K >> 6;

    const int lrow = tid >> 1, lhalf = tid & 1;

    float acc[2][NT][4];
#pragma unroll
    for (int i = 0; i < 2; i++)
#pragma unroll
        for (int j = 0; j < NT; j++)
#pragma unroll
            for (int q = 0; q < 4; q++) acc[i][j][q] = 0.f;

    const uint32_t aoff = (uint32_t)(m_base + (lane & 15)) * STR + (uint32_t)(lane >> 4) * 16;
    const uint32_t boff = (uint32_t)(n_base + ((lane >> 4) & 1) * 8 + (lane & 7)) * STR +
                          (uint32_t)((lane >> 3) & 1) * 16;

    for (int c = 0; c < nch; c++) {
        if (c) __syncthreads();
        const int k0 = c * 64;
        {
            int gr = m0 + lrow;
            uint4 h[4], l[4];
            if (gr < M) {
                const float4* srcp = (const float4*)(A + (size_t)gr * K + k0 + lhalf * 32);
#pragma unroll
                for (int j = 0; j < 4; j++) cvt8(srcp[2 * j], srcp[2 * j + 1], h[j], l[j]);
            } else {
#pragma unroll
                for (int j = 0; j < 4; j++) { h[j] = make_uint4(0,0,0,0); l[j] = make_uint4(0,0,0,0); }
            }
#pragma unroll
            for (int j = 0; j < 4; j++) {
                uint32_t off = lrow * STR + lhalf * 64 + j * 16;
                *(uint4*)(sm + OA_HI + off) = h[j];
                *(uint4*)(sm + OA_LO + off) = l[j];
            }
        }
        if (lrow < BN) {
            const uint4* sh = (const uint4*)(Bhi + (size_t)(n0 + lrow) * K + k0 + lhalf * 32);
            const uint4* sl = (const uint4*)(Blo + (size_t)(n0 + lrow) * K + k0 + lhalf * 32);
#pragma unroll
            for (int j = 0; j < 4; j++) {
                uint32_t off = lrow * STR + lhalf * 64 + j * 16;
                *(uint4*)(sm + OB_HI + off) = sh[j];
                *(uint4*)(sm + OB_LO + off) = sl[j];
            }
        }
        __syncthreads();

#pragma unroll
        for (int k16 = 0; k16 < 4; k16++) {
            uint32_t aH[2][4], aL[2][4];
#pragma unroll
            for (int mi = 0; mi < 2; mi++) {
                uint32_t ad = smb + aoff + mi * (16 * STR) + k16 * 32;
                ldsm4(aH[mi], ad + OA_HI);
                ldsm4(aL[mi], ad + OA_LO);
            }
#pragma unroll
            for (int pr = 0; pr < NT / 2; pr++) {
                uint32_t bH[4], bL[4];
                uint32_t bd = smb + boff + pr * (16 * STR) + k16 * 32;
                ldsm4(bH, bd + OB_HI);
                ldsm4(bL, bd + OB_LO);
#pragma unroll
                for (int mi = 0; mi < 2; mi++)
#pragma unroll
                    for (int t = 0; t < 2; t++) {
                        int nt = pr * 2 + t;
                        mma_bf16(acc[mi][nt], aH[mi], bH + 2 * t);
                        mma_bf16(acc[mi][nt], aH[mi], bL + 2 * t);
                        mma_bf16(acc[mi][nt], aL[mi], bH + 2 * t);
                    }
            }
        }
    }

    float* Cb = (cSel == 1) ? g_xA : (cSel == 2) ? g_xB : g_h;
#pragma unroll
    for (int mi = 0; mi < 2; mi++) {
#pragma unroll
        for (int nt = 0; nt < NT; nt++) {
            int colL = n_base + nt * 8 + (lane & 3) * 2;
            int gcolL = n0 + colL;
            int bidx = (cmode == 1) ? (gcolL & 255) : (cbase + gcolL);
            float b0 = bias[bidx], b1 = bias[bidx + 1];
#pragma unroll
            for (int half = 0; half < 2; half++) {
                int gr = m0 + m_base + mi * 16 + (lane >> 2) + half * 8;
                if (gr < M) {
                    float2 v;
                    v.x = actf(acc[mi][nt][half * 2 + 0] + b0, act);
                    v.y = actf(acc[mi][nt][half * 2 + 1] + b1, act);
                    float* cp;
                    if (cmode == 1) {
                        int seg = gcolL >> 8, lc = gcolL & 255;
                        cp = Cb + ((size_t)seg * M + gr) * 256 + lc;
                    } else {
                        cp = Cb + (size_t)gr * ldc + cbase + gcolL;
                    }
                    *(float2*)cp = v;
                }
            }
        }
    }
}

// ---------------- small projection (K=5/3) -----------------------------------
__global__ void k_projsmall(const float* __restrict__ A, int K,
                            const float* __restrict__ W,
                            const float* __restrict__ bias, int coloff)
{
    int id = blockIdx.x * blockDim.x + threadIdx.x;
    if (id >= NN * 64) return;
    int n = id >> 6, j = id & 63;
    float s = bias[j];
    for (int k = 0; k < K; k++) s += A[(size_t)n * K + k] * W[k * 64 + j];
    g_xA[(size_t)n * HD + coloff + j] = actf(s, 1);
}

// ---------------- CSR build ---------------------------------------------------
__global__ void k_zero_cnt() {
    int id = blockIdx.x * blockDim.x + threadIdx.x;
    if (id < 2 * NN) g_cnt[id] = 0;
}
__global__ void k_count(const int* __restrict__ dst, const int* __restrict__ et) {
    int e = blockIdx.x * blockDim.x + threadIdx.x;
    if (e >= EE) return;
    atomicAdd(&g_cnt[et[e] * NN + dst[e]], 1);
}
// single-block exclusive scan over 2*NN counts -> g_off, g_cursor
__global__ void k_scan() {
    __shared__ int part[1024];
    const int T = 1024;
    const int CH = (2 * NN + T - 1) / T;     // 98
    int t = threadIdx.x;
    int base = t * CH;
    int s = 0;
    for (int i = 0; i < CH; i++) {
        int idx = base + i;
        if (idx < 2 * NN) s += g_cnt[idx];
    }
    part[t] = s;
    __syncthreads();
    for (int off = 1; off < T; off <<= 1) {
        int v = (t >= off) ? part[t - off] : 0;
        __syncthreads();
        part[t] += v;
        __syncthreads();
    }
    int run = (t == 0) ? 0 : part[t - 1];
    for (int i = 0; i < CH; i++) {
        int idx = base + i;
        if (idx < 2 * NN) {
            g_off[idx] = run;
            g_cursor[idx] = run;
            run += g_cnt[idx];
        }
    }
    if (t == T - 1) g_off[2 * NN] = run;
}
__global__ void k_fill(const int* __restrict__ src, const int* __restrict__ dst,
                       const int* __restrict__ et) {
    int e = blockIdx.x * blockDim.x + threadIdx.x;
    if (e >= EE) return;
    int seg = et[e] * NN + dst[e];
    int pos = atomicAdd(&g_cursor[seg], 1);
    g_eidx[pos] = src[e];
}

// ---------------- fused gather-aggregate (no atomics) -------------------------
// one warp per node: x_out[n] = h_root[n] + mean_{e: r0->n} h_r0[src] + mean_{e: r1->n} h_r1[src]
__global__ void __launch_bounds__(256) k_aggregate(int outSel) {
    int gw = (blockIdx.x * blockDim.x + threadIdx.x) >> 5;
    int lane = threadIdx.x & 31;
    if (gw >= NN) return;

    const float4* rootp = (const float4*)(g_h + ((size_t)2 * NN + gw) * HD);
    float4 a0 = rootp[lane];
    float4 a1 = rootp[lane + 32];

#pragma unroll
    for (int rel = 0; rel < 2; rel++) {
        int s0 = g_off[rel * NN + gw];
        int s1 = g_off[rel * NN + gw + 1];
        float4 t0 = make_float4(0.f, 0.f, 0.f, 0.f);
        float4 t1 = make_float4(0.f, 0.f, 0.f, 0.f);
        const float* hb = g_h + (size_t)rel * NN * HD;
        for (int i = s0; i < s1; i++) {
            int sn = __ldg(&g_eidx[i]);
            const float4* rp = (const float4*)(hb + (size_t)sn * HD);
            float4 v0 = rp[lane];
            float4 v1 = rp[lane + 32];
            t0.x += v0.x; t0.y += v0.y; t0.z += v0.z; t0.w += v0.w;
            t1.x += v1.x; t1.y += v1.y; t1.z += v1.z; t1.w += v1.w;
        }
        int deg = s1 - s0;
        float inv = 1.f / (float)(deg > 0 ? deg : 1);
        a0.x += t0.x * inv; a0.y += t0.y * inv; a0.z += t0.z * inv; a0.w += t0.w * inv;
        a1.x += t1.x * inv; a1.y += t1.y * inv; a1.z += t1.z * inv; a1.w += t1.w * inv;
    }

    float* xout = outSel ? g_xB : g_xA;
    float4* op = (float4*)(xout + (size_t)gw * HD);
    op[lane] = a0;
    op[lane + 32] = a1;
}

// ---------------- head --------------------------------------------------------
__global__ void k_out(const float* __restrict__ W,
                      const float* __restrict__ b,
                      float* __restrict__ out)
{
    int g = blockIdx.x * blockDim.x + threadIdx.x;
    int n = g >> 5, lane = g & 31;
    if (n >= NN) return;
    const float* xr = g_xB + (size_t)n * HD;
    float s0 = 0.f, s1 = 0.f;
#pragma unroll
    for (int j = lane; j < HD; j += 32) {
        float v = xr[j];
        float2 w = *(const float2*)(W + j * 2);
        s0 += v * w.x;
        s1 += v * w.y;
    }
#pragma unroll
    for (int o = 16; o; o >>= 1) {
        s0 += __shfl_down_sync(0xFFFFFFFFu, s0, o);
        s1 += __shfl_down_sync(0xFFFFFFFFu, s1, o);
    }
    if (lane == 0) {
        out[(size_t)n * 2 + 0] = s0 + b[0];
        out[(size_t)n * 2 + 1] = s1 + b[1];
    }
}

// ---------------- launch ------------------------------------------------------
extern "C" void kernel_launch(void* const* d_in, const int* in_sizes, int n_in,
                              void* d_out, int out_size)
{
    const float* des   = (const float*)d_in[0];
    const float* tweet = (const float*)d_in[1];
    const float* nump  = (const float*)d_in[2];
    const float* catp  = (const float*)d_in[3];
    const int*   ei    = (const int*)d_in[4];
    const int*   et    = (const int*)d_in[5];
    const float* w_des = (const float*)d_in[6];
    const float* b_des = (const float*)d_in[7];
    const float* w_tw  = (const float*)d_in[8];
    const float* b_tw  = (const float*)d_in[9];
    const float* w_num = (const float*)d_in[10];
    const float* b_num = (const float*)d_in[11];
    const float* w_cat = (const float*)d_in[12];
    const float* b_cat = (const float*)d_in[13];
    const float* w_in  = (const float*)d_in[14];
    const float* b_in  = (const float*)d_in[15];
    const float* wt1   = (const float*)d_in[16];
    const float* rt1   = (const float*)d_in[17];
    const float* bs1   = (const float*)d_in[18];
    const float* wt2   = (const float*)d_in[19];
    const float* rt2   = (const float*)d_in[20];
    const float* bs2   = (const float*)d_in[21];
    const float* w_out = (const float*)d_in[22];
    const float* b_out = (const float*)d_in[23];
    float* out = (float*)d_out;

    const int* src = ei;
    const int* dst = ei + EE;

    const int SZ128 = 4 * 18432;                    // 73728
    const int SZ64  = 2 * 18432 + 2 * 9216;         // 55296
    cudaFuncSetAttribute(k_gemm_mma<128>, cudaFuncAttributeMaxDynamicSharedMemorySize, SZ128);
    cudaFuncSetAttribute(k_gemm_mma<64>,  cudaFuncAttributeMaxDynamicSharedMemorySize, SZ64);

    // weight prep (transpose + bf16 hi/lo split)
    k_wprep768<<<(768 * 64 + 255) / 256, 256>>>(w_des, OFF_DES);
    k_wprep768<<<(768 * 64 + 255) / 256, 256>>>(w_tw, OFF_TW);
    k_wprep_all<<<dim3((256 * 256 + 255) / 256, 7), 256>>>(w_in, wt1, rt1, wt2, rt2);

    // CSR build (shared by both layers)
    k_zero_cnt<<<(2 * NN + 255) / 256, 256>>>();
    k_count<<<(EE + 255) / 256, 256>>>(dst, et);
    k_scan<<<1, 1024>>>();
    k_fill<<<(EE + 255) / 256, 256>>>(src, dst, et);

    const int MB = (NN + 127) / 128;  // 391 row tiles

    // feature projections -> g_xA
    k_gemm_mma<64><<<dim3(1, MB), 256, SZ64>>>(des, 0, 768, NN, OFF_DES, b_des, 1, 0, HD, 0, 1);
    k_gemm_mma<64><<<dim3(1, MB), 256, SZ64>>>(tweet, 0, 768, NN, OFF_TW, b_tw, 1, 64, HD, 0, 1);
    {
        int th = NN * 64, bl = (th + 255) / 256;
        k_projsmall<<<bl, 256>>>(nump, 5, w_num, b_num, 128);
        k_projsmall<<<bl, 256>>>(catp, 3, w_cat, b_cat, 192);
    }

    // x = lrelu(xA @ w_in + b_in) -> g_xB
    k_gemm_mma<128><<<dim3(2, MB), 256, SZ128>>>(nullptr, 1, 256, NN, OFF_WIN, b_in, 2, 0, HD, 0, 1);

    const int agBl = (NN * 32 + 255) / 256;

    // RGCN layer 1: in g_xB -> out g_xA
    k_gemm_mma<128><<<dim3(6, MB), 256, SZ128>>>(nullptr, 2, 256, NN, OFF_R1, bs1, 3, 0, HD, 1, 2);
    k_aggregate<<<agBl, 256>>>(0);

    // RGCN layer 2: in g_xA -> out g_xB
    k_gemm_mma<128><<<dim3(6, MB), 256, SZ128>>>(nullptr, 1, 256, NN, OFF_R2, bs2, 3, 0, HD, 1, 2);
    k_aggregate<<<agBl, 256>>>(1);

    // head
    k_out<<<(NN * 32 + 255) / 256, 256>>>(w_out, b_out, out);
}

// round 8
// speedup vs baseline: 2.1043x; 1.0978x over previous
#include <cuda_runtime.h>
#include <cuda_bf16.h>
#include <cstdint>

#define NN 50000
#define NP 50048          // padded rows (multiple of 128) for unguarded cp.async
#define EE 800000
#define HD 256
#define DESW 768

// ---------------- scratch (device globals; no runtime alloc) ----------------
// activations as bf16 hi/lo, 2 slots each
__device__ __align__(16) __nv_bfloat16 g_xh[(size_t)2 * NP * HD];
__device__ __align__(16) __nv_bfloat16 g_xl[(size_t)2 * NP * HD];
__device__ __align__(16) float g_h[(size_t)3 * NN * HD];     // [rel0 | rel1 | root] fp32
__device__ __align__(16) int   g_cnt[2 * NN];
__device__ __align__(16) int   g_off[2 * NN + 1];
__device__ __align__(16) int   g_cursor[2 * NN];
__device__ __align__(16) int   g_eidx[EE];

// transposed bf16 hi/lo weight store (B as [N,K] K-major)
#define OFF_DES 0
#define OFF_TW  49152
#define OFF_WIN 98304
#define OFF_R1  163840
#define OFF_R2  360448
__device__ __align__(16) __nv_bfloat16 g_whi[557056];
__device__ __align__(16) __nv_bfloat16 g_wlo[557056];

// ---------------- helpers -----------------------------------------------------
__device__ __forceinline__ uint32_t smem_u32(const void* p) {
    uint32_t a;
    asm("{ .reg .u64 t; cvta.to.shared.u64 t, %1; cvt.u32.u64 %0, t; }" : "=r"(a) : "l"(p));
    return a;
}
__device__ __forceinline__ void ldsm4(uint32_t* r, uint32_t addr) {
    asm volatile("ldmatrix.sync.aligned.m8n8.x4.shared.b16 {%0,%1,%2,%3}, [%4];"
                 : "=r"(r[0]), "=r"(r[1]), "=r"(r[2]), "=r"(r[3]) : "r"(addr));
}
__device__ __forceinline__ void mma_bf16(float* c, const uint32_t* a, const uint32_t* b) {
    asm volatile(
        "mma.sync.aligned.m16n8k16.row.col.f32.bf16.bf16.f32 "
        "{%0,%1,%2,%3}, {%4,%5,%6,%7}, {%8,%9}, {%0,%1,%2,%3};"
        : "+f"(c[0]), "+f"(c[1]), "+f"(c[2]), "+f"(c[3])
        : "r"(a[0]), "r"(a[1]), "r"(a[2]), "r"(a[3]), "r"(b[0]), "r"(b[1]));
}
__device__ __forceinline__ void cpa16(uint32_t dst, const void* src) {
    asm volatile("cp.async.cg.shared.global [%0], [%1], 16;" :: "r"(dst), "l"(src));
}
__device__ __forceinline__ void cp_commit() {
    asm volatile("cp.async.commit_group;" ::: "memory");
}
template <int N>
__device__ __forceinline__ void cp_wait() {
    asm volatile("cp.async.wait_group %0;" :: "n"(N) : "memory");
}
__device__ __forceinline__ float actf(float v, int act) {
    if (act == 1) return v > 0.f ? v : 0.01f * v;
    if (act == 2) return v > 0.f ? v : 0.f;
    return v;
}
__device__ __forceinline__ void pack_hilo(float a, float b, uint32_t& hw, uint32_t& lw) {
    __nv_bfloat16 h0 = __float2bfloat16_rn(a), h1 = __float2bfloat16_rn(b);
    float l0 = a - __bfloat162float(h0), l1 = b - __bfloat162float(h1);
    hw = (uint32_t)__bfloat16_as_ushort(h0) | ((uint32_t)__bfloat16_as_ushort(h1) << 16);
    lw = (uint32_t)__bfloat16_as_ushort(__float2bfloat16_rn(l0)) |
         ((uint32_t)__bfloat16_as_ushort(__float2bfloat16_rn(l1)) << 16);
}
// 8 fp32 -> 8 bf16 hi + 8 bf16 lo, packed as uint4 (for external fp32 A)
__device__ __forceinline__ void cvt8(float4 x, float4 y, uint4& h, uint4& l) {
    float v[8] = {x.x, x.y, x.z, x.w, y.x, y.y, y.z, y.w};
    uint32_t hb[8], lb[8];
#pragma unroll
    for (int i = 0; i < 8; i++) {
        __nv_bfloat16 hh = __float2bfloat16_rn(v[i]);
        hb[i] = (uint32_t)__bfloat16_as_ushort(hh);
        float r = v[i] - __bfloat162float(hh);
        lb[i] = (uint32_t)__bfloat16_as_ushort(__float2bfloat16_rn(r));
    }
    h.x = hb[0] | (hb[1] << 16); h.y = hb[2] | (hb[3] << 16);
    h.z = hb[4] | (hb[5] << 16); h.w = hb[6] | (hb[7] << 16);
    l.x = lb[0] | (lb[1] << 16); l.y = lb[2] | (lb[3] << 16);
    l.z = lb[4] | (lb[5] << 16); l.w = lb[6] | (lb[7] << 16);
}

// ---------------- weight prep -------------------------------------------------
__device__ __forceinline__ void wprep_one(const float* W, int K, int N, int outOff, int id) {
    int k = id / N, n = id - k * N;
    float w = W[id];
    __nv_bfloat16 h = __float2bfloat16_rn(w);
    float lo = w - __bfloat162float(h);
    g_whi[(size_t)outOff + (size_t)n * K + k] = h;
    g_wlo[(size_t)outOff + (size_t)n * K + k] = __float2bfloat16_rn(lo);
}
__global__ void k_wprep768(const float* __restrict__ W, int outOff) {
    int id = blockIdx.x * blockDim.x + threadIdx.x;
    if (id < 768 * 64) wprep_one(W, 768, 64, outOff, id);
}
__global__ void k_wprep_all(const float* __restrict__ w_in, const float* __restrict__ wt1,
                            const float* __restrict__ rt1, const float* __restrict__ wt2,
                            const float* __restrict__ rt2) {
    int id = blockIdx.x * blockDim.x + threadIdx.x;
    if (id >= 256 * 256) return;
    int y = blockIdx.y;
    const float* W;
    int off;
    switch (y) {
        case 0: W = w_in;          off = OFF_WIN;           break;
        case 1: W = wt1;           off = OFF_R1;            break;
        case 2: W = wt1 + 65536;   off = OFF_R1 + 65536;    break;
        case 3: W = rt1;           off = OFF_R1 + 131072;   break;
        case 4: W = wt2;           off = OFF_R2;            break;
        case 5: W = wt2 + 65536;   off = OFF_R2 + 65536;    break;
        default: W = rt2;          off = OFF_R2 + 131072;   break;
    }
    wprep_one(W, 256, 256, off, id);
}

// ---------------- cp.async double-buffered bf16-split GEMM --------------------
// AMODE 0: A = external fp32 (cvt in-kernel, synchronous stage)
// AMODE 1: A = bf16 hi/lo slot (cp.async)
// cmode 0: writes bf16 hi/lo x slot (cSel 1/2); cmode 1: fp32 seg-split g_h.
template <int BN, int AMODE>
__global__ void __launch_bounds__(256) k_gemm_mma(
    const float* __restrict__ Aparam, int aSlot, int K, int M, int bOff,
    const float* __restrict__ bias, int cSel, int cbase, int cmode, int act)
{
    extern __shared__ char sm[];
    constexpr int STR = 144;
    constexpr int ABUF = 128 * STR;          // 18432 per buffer
    constexpr int BBUF = BN * STR;
    constexpr int NT = BN / 16;

    const uint32_t smb = smem_u32(sm);
    const int tid = threadIdx.x;
    const int lane = tid & 31, wid = tid >> 5;
    const int m_base = (wid & 3) * 32;
    const int n_base = (wid >> 2) * (BN / 2);

    const __nv_bfloat16* Ah = g_xh + (size_t)aSlot * NP * HD;
    const __nv_bfloat16* Al = g_xl + (size_t)aSlot * NP * HD;
    const __nv_bfloat16* Bhi = g_whi + bOff;
    const __nv_bfloat16* Blo = g_wlo + bOff;

    const int m0 = blockIdx.y * 128;
    const int n0 = blockIdx.x * BN;
    const int nch = K >> 6;

    const int lrow = tid >> 1, lhalf = tid & 1;

    float acc[2][NT][4];
#pragma unroll
    for (int i = 0; i < 2; i++)
#pragma unroll
        for (int j = 0; j < NT; j++)
#pragma unroll
            for (int q = 0; q < 4; q++) acc[i][j][q] = 0.f;

    const uint32_t aoff = (uint32_t)(m_base + (lane & 15)) * STR + (uint32_t)(lane >> 4) * 16;
    const uint32_t boff = (uint32_t)(n_base + ((lane >> 4) & 1) * 8 + (lane & 7)) * STR +
                          (uint32_t)((lane >> 3) & 1) * 16;

    // async loaders
    auto loadA = [&](int c, int buf) {
        if (AMODE == 1) {
            int k0 = c * 64;
            size_t base = (size_t)(m0 + lrow) * HD + k0 + lhalf * 32;
            uint32_t d = smb + buf * ABUF + lrow * STR + lhalf * 64;
            uint32_t d2 = d + 2 * ABUF;
#pragma unroll
            for (int j = 0; j < 4; j++) {
                cpa16(d + j * 16, Ah + base + j * 8);
                cpa16(d2 + j * 16, Al + base + j * 8);
            }
        }
    };
    auto loadB = [&](int c, int buf) {
        if (lrow < BN) {
            int k0 = c * 64;
            size_t base = (size_t)(n0 + lrow) * K + k0 + lhalf * 32;
            uint32_t d = smb + 4 * ABUF + buf * BBUF + lrow * STR + lhalf * 64;
            uint32_t d2 = d + 2 * BBUF;
#pragma unroll
            for (int j = 0; j < 4; j++) {
                cpa16(d + j * 16, Bhi + base + j * 8);
                cpa16(d2 + j * 16, Blo + base + j * 8);
            }
        }
    };

    loadA(0, 0);
    loadB(0, 0);
    cp_commit();

    for (int c = 0; c < nch; c++) {
        const int buf = c & 1;
        if (c + 1 < nch) {
            loadA(c + 1, buf ^ 1);
            loadB(c + 1, buf ^ 1);
            cp_commit();
            cp_wait<1>();
        } else {
            cp_wait<0>();
        }
        __syncthreads();

        if (AMODE == 0) {
            // synchronous fp32 -> bf16 hi/lo stage into buffer `buf`
            int gr = m0 + lrow;
            int k0 = c * 64;
            uint4 h[4], l[4];
            if (gr < M) {
                const float4* srcp = (const float4*)(Aparam + (size_t)gr * K + k0 + lhalf * 32);
#pragma unroll
                for (int j = 0; j < 4; j++) cvt8(srcp[2 * j], srcp[2 * j + 1], h[j], l[j]);
            } else {
#pragma unroll
                for (int j = 0; j < 4; j++) { h[j] = make_uint4(0,0,0,0); l[j] = make_uint4(0,0,0,0); }
            }
#pragma unroll
            for (int j = 0; j < 4; j++) {
                uint32_t off = buf * ABUF + lrow * STR + lhalf * 64 + j * 16;
                *(uint4*)(sm + off) = h[j];
                *(uint4*)(sm + 2 * ABUF + off) = l[j];
            }
            __syncthreads();
        }

        const uint32_t abH = smb + buf * ABUF;
        const uint32_t abL = abH + 2 * ABUF;
        const uint32_t bbH = smb + 4 * ABUF + buf * BBUF;
        const uint32_t bbL = bbH + 2 * BBUF;

#pragma unroll
        for (int k16 = 0; k16 < 4; k16++) {
            uint32_t aH[2][4], aL[2][4];
#pragma unroll
            for (int mi = 0; mi < 2; mi++) {
                uint32_t ad = aoff + mi * (16 * STR) + k16 * 32;
                ldsm4(aH[mi], abH + ad);
                ldsm4(aL[mi], abL + ad);
            }
#pragma unroll
            for (int pr = 0; pr < NT / 2; pr++) {
                uint32_t bH[4], bL[4];
                uint32_t bd = boff + pr * (16 * STR) + k16 * 32;
                ldsm4(bH, bbH + bd);
                ldsm4(bL, bbL + bd);
#pragma unroll
                for (int mi = 0; mi < 2; mi++)
#pragma unroll
                    for (int t = 0; t < 2; t++) {
                        int nt = pr * 2 + t;
                        mma_bf16(acc[mi][nt], aH[mi], bH + 2 * t);
                        mma_bf16(acc[mi][nt], aH[mi], bL + 2 * t);
                        mma_bf16(acc[mi][nt], aL[mi], bH + 2 * t);
                    }
            }
        }
        __syncthreads();
    }

    // ---- epilogue ----
#pragma unroll
    for (int mi = 0; mi < 2; mi++) {
#pragma unroll
        for (int nt = 0; nt < NT; nt++) {
            int colL = n_base + nt * 8 + (lane & 3) * 2;
            int gcolL = n0 + colL;
            int bidx = (cmode == 1) ? (gcolL & 255) : (cbase + gcolL);
            float b0 = bias[bidx], b1 = bias[bidx + 1];
#pragma unroll
            for (int half = 0; half < 2; half++) {
                int gr = m0 + m_base + mi * 16 + (lane >> 2) + half * 8;
                if (gr < M) {
                    float vx = actf(acc[mi][nt][half * 2 + 0] + b0, act);
                    float vy = actf(acc[mi][nt][half * 2 + 1] + b1, act);
                    if (cmode == 1) {
                        int seg = gcolL >> 8, lc = gcolL & 255;
                        float* cp = g_h + ((size_t)seg * M + gr) * 256 + lc;
                        *(float2*)cp = make_float2(vx, vy);
                    } else {
                        int slot = cSel - 1;
                        size_t eoff = (size_t)slot * NP * HD + (size_t)gr * HD + cbase + gcolL;
                        uint32_t hw, lw;
                        pack_hilo(vx, vy, hw, lw);
                        *(uint32_t*)(g_xh + eoff) = hw;
                        *(uint32_t*)(g_xl + eoff) = lw;
                    }
                }
            }
        }
    }
}

// ---------------- small projection (K=5/3) -> slot0 bf16 hi/lo ---------------
__global__ void k_projsmall(const float* __restrict__ A, int K,
                            const float* __restrict__ W,
                            const float* __restrict__ bias, int coloff)
{
    int id = blockIdx.x * blockDim.x + threadIdx.x;
    if (id >= NN * 64) return;
    int n = id >> 6, j = id & 63;
    float s = bias[j];
    for (int k = 0; k < K; k++) s += A[(size_t)n * K + k] * W[k * 64 + j];
    s = actf(s, 1);
    __nv_bfloat16 h = __float2bfloat16_rn(s);
    float lo = s - __bfloat162float(h);
    size_t eoff = (size_t)n * HD + coloff + j;
    g_xh[eoff] = h;
    g_xl[eoff] = __float2bfloat16_rn(lo);
}

// ---------------- CSR build ---------------------------------------------------
__global__ void k_zero_cnt() {
    int id = blockIdx.x * blockDim.x + threadIdx.x;
    if (id < 2 * NN) g_cnt[id] = 0;
}
__global__ void k_count(const int* __restrict__ dst, const int* __restrict__ et) {
    int e = blockIdx.x * blockDim.x + threadIdx.x;
    if (e >= EE) return;
    atomicAdd(&g_cnt[et[e] * NN + dst[e]], 1);
}
__global__ void k_scan() {
    __shared__ int part[1024];
    const int T = 1024;
    const int CH = (2 * NN + T - 1) / T;
    int t = threadIdx.x;
    int base = t * CH;
    int s = 0;
    for (int i = 0; i < CH; i++) {
        int idx = base + i;
        if (idx < 2 * NN) s += g_cnt[idx];
    }
    part[t] = s;
    __syncthreads();
    for (int off = 1; off < T; off <<= 1) {
        int v = (t >= off) ? part[t - off] : 0;
        __syncthreads();
        part[t] += v;
        __syncthreads();
    }
    int run = (t == 0) ? 0 : part[t - 1];
    for (int i = 0; i < CH; i++) {
        int idx = base + i;
        if (idx < 2 * NN) {
            g_off[idx] = run;
            g_cursor[idx] = run;
            run += g_cnt[idx];
        }
    }
    if (t == T - 1) g_off[2 * NN] = run;
}
__global__ void k_fill(const int* __restrict__ src, const int* __restrict__ dst,
                       const int* __restrict__ et) {
    int e = blockIdx.x * blockDim.x + threadIdx.x;
    if (e >= EE) return;
    int seg = et[e] * NN + dst[e];
    int pos = atomicAdd(&g_cursor[seg], 1);
    g_eidx[pos] = src[e];
}

// ---------------- fused gather-aggregate --------------------------------------
// one warp per node. FINAL=0: write x (bf16 hi/lo) to outSlot. FINAL=1: head logits.
template <int FINAL>
__global__ void __launch_bounds__(256) k_aggregate(int outSlot,
                                                   const float* __restrict__ Wout,
                                                   const float* __restrict__ bout,
                                                   float* __restrict__ out)
{
    int gw = (blockIdx.x * blockDim.x + threadIdx.x) >> 5;
    int lane = threadIdx.x & 31;
    if (gw >= NN) return;

    const float4* rootp = (const float4*)(g_h + ((size_t)2 * NN + gw) * HD);
    float4 a0 = rootp[lane];
    float4 a1 = rootp[lane + 32];

#pragma unroll
    for (int rel = 0; rel < 2; rel++) {
        int s0 = g_off[rel * NN + gw];
        int s1 = g_off[rel * NN + gw + 1];
        float4 t0 = make_float4(0.f, 0.f, 0.f, 0.f);
        float4 t1 = make_float4(0.f, 0.f, 0.f, 0.f);
        const float* hb = g_h + (size_t)rel * NN * HD;
        for (int i = s0; i < s1; i++) {
            int sn = __ldg(&g_eidx[i]);
            const float4* rp = (const float4*)(hb + (size_t)sn * HD);
            float4 v0 = rp[lane];
            float4 v1 = rp[lane + 32];
            t0.x += v0.x; t0.y += v0.y; t0.z += v0.z; t0.w += v0.w;
            t1.x += v1.x; t1.y += v1.y; t1.z += v1.z; t1.w += v1.w;
        }
        int deg = s1 - s0;
        float inv = 1.f / (float)(deg > 0 ? deg : 1);
        a0.x += t0.x * inv; a0.y += t0.y * inv; a0.z += t0.z * inv; a0.w += t0.w * inv;
        a1.x += t1.x * inv; a1.y += t1.y * inv; a1.z += t1.z * inv; a1.w += t1.w * inv;
    }

    if (FINAL == 0) {
        size_t eoff = (size_t)outSlot * NP * HD + (size_t)gw * HD + lane * 4;
        uint32_t h0, l0, h1, l1;
        pack_hilo(a0.x, a0.y, h0, l0);
        pack_hilo(a0.z, a0.w, h1, l1);
        *(uint2*)(g_xh + eoff) = make_uint2(h0, h1);
        *(uint2*)(g_xl + eoff) = make_uint2(l0, l1);
        pack_hilo(a1.x, a1.y, h0, l0);
        pack_hilo(a1.z, a1.w, h1, l1);
        *(uint2*)(g_xh + eoff + 128) = make_uint2(h0, h1);
        *(uint2*)(g_xl + eoff + 128) = make_uint2(l0, l1);
    } else {
        float va[4] = {a0.x, a0.y, a0.z, a0.w};
        float vb[4] = {a1.x, a1.y, a1.z, a1.w};
        float s0 = 0.f, s1 = 0.f;
        int c0 = lane * 4;
#pragma unroll
        for (int q = 0; q < 4; q++) {
            float2 w = *(const float2*)(Wout + (c0 + q) * 2);
            s0 += va[q] * w.x; s1 += va[q] * w.y;
            float2 w2 = *(const float2*)(Wout + (128 + c0 + q) * 2);
            s0 += vb[q] * w2.x; s1 += vb[q] * w2.y;
        }
#pragma unroll
        for (int o = 16; o; o >>= 1) {
            s0 += __shfl_down_sync(0xFFFFFFFFu, s0, o);
            s1 += __shfl_down_sync(0xFFFFFFFFu, s1, o);
        }
        if (lane == 0) {
            out[(size_t)gw * 2 + 0] = s0 + bout[0];
            out[(size_t)gw * 2 + 1] = s1 + bout[1];
        }
    }
}

// ---------------- launch ------------------------------------------------------
extern "C" void kernel_launch(void* const* d_in, const int* in_sizes, int n_in,
                              void* d_out, int out_size)
{
    const float* des   = (const float*)d_in[0];
    const float* tweet = (const float*)d_in[1];
    const float* nump  = (const float*)d_in[2];
    const float* catp  = (const float*)d_in[3];
    const int*   ei    = (const int*)d_in[4];
    const int*   et    = (const int*)d_in[5];
    const float* w_des = (const float*)d_in[6];
    const float* b_des = (const float*)d_in[7];
    const float* w_tw  = (const float*)d_in[8];
    const float* b_tw  = (const float*)d_in[9];
    const float* w_num = (const float*)d_in[10];
    const float* b_num = (const float*)d_in[11];
    const float* w_cat = (const float*)d_in[12];
    const float* b_cat = (const float*)d_in[13];
    const float* w_in  = (const float*)d_in[14];
    const float* b_in  = (const float*)d_in[15];
    const float* wt1   = (const float*)d_in[16];
    const float* rt1   = (const float*)d_in[17];
    const float* bs1   = (const float*)d_in[18];
    const float* wt2   = (const float*)d_in[19];
    const float* rt2   = (const float*)d_in[20];
    const float* bs2   = (const float*)d_in[21];
    const float* w_out = (const float*)d_in[22];
    const float* b_out = (const float*)d_in[23];
    float* out = (float*)d_out;

    const int* src = ei;
    const int* dst = ei + EE;

    const int SZ128 = 4 * 18432 + 4 * 128 * 144;    // 147456
    const int SZ64  = 4 * 18432 + 4 * 64 * 144;     // 110592
    cudaFuncSetAttribute(k_gemm_mma<128, 1>, cudaFuncAttributeMaxDynamicSharedMemorySize, SZ128);
    cudaFuncSetAttribute(k_gemm_mma<64, 0>,  cudaFuncAttributeMaxDynamicSharedMemorySize, SZ64);

    // weight prep
    k_wprep768<<<(768 * 64 + 255) / 256, 256>>>(w_des, OFF_DES);
    k_wprep768<<<(768 * 64 + 255) / 256, 256>>>(w_tw, OFF_TW);
    k_wprep_all<<<dim3((256 * 256 + 255) / 256, 7), 256>>>(w_in, wt1, rt1, wt2, rt2);

    // CSR build
    k_zero_cnt<<<(2 * NN + 255) / 256, 256>>>();
    k_count<<<(EE + 255) / 256, 256>>>(dst, et);
    k_scan<<<1, 1024>>>();
    k_fill<<<(EE + 255) / 256, 256>>>(src, dst, et);

    const int MB = (NN + 127) / 128;  // 391 row tiles

    // feature projections -> slot0
    k_gemm_mma<64, 0><<<dim3(1, MB), 256, SZ64>>>(des, 0, 768, NN, OFF_DES, b_des, 1, 0, 0, 1);
    k_gemm_mma<64, 0><<<dim3(1, MB), 256, SZ64>>>(tweet, 0, 768, NN, OFF_TW, b_tw, 1, 64, 0, 1);
    {
        int th = NN * 64, bl = (th + 255) / 256;
        k_projsmall<<<bl, 256>>>(nump, 5, w_num, b_num, 128);
        k_projsmall<<<bl, 256>>>(catp, 3, w_cat, b_cat, 192);
    }

    // x = lrelu(slot0 @ w_in + b_in) -> slot1
    k_gemm_mma<128, 1><<<dim3(2, MB), 256, SZ128>>>(nullptr, 0, 256, NN, OFF_WIN, b_in, 2, 0, 0, 1);

    const int agBl = (NN * 32 + 255) / 256;

    // RGCN layer 1: slot1 -> g_h -> slot0
    k_gemm_mma<128, 1><<<dim3(6, MB), 256, SZ128>>>(nullptr, 1, 256, NN, OFF_R1, bs1, 3, 0, 1, 2);
    k_aggregate<0><<<agBl, 256>>>(0, nullptr, nullptr, nullptr);

    // RGCN layer 2: slot0 -> g_h -> head logits (fused)
    k_gemm_mma<128, 1><<<dim3(6, MB), 256, SZ128>>>(nullptr, 0, 256, NN, OFF_R2, bs2, 3, 0, 1, 2);
    k_aggregate<1><<<agBl, 256>>>(0, w_out, b_out, out);
}